// round 1
// baseline (speedup 1.0000x reference)
#include <cuda_runtime.h>
#include <math.h>
#include <stddef.h>

// Problem constants
#define BB 4
#define SS 2048
#define DD 1024
#define MTOT (BB * SS)          // 8192
#define LN_EPS 1e-5f
#define INV_SCALE 0.125f        // 1/sqrt(64)

// ---------------- scratch (device globals; no allocation allowed) ----------
__device__ float g_Q [MTOT * DD];
__device__ float g_K [MTOT * DD];
__device__ float g_V [MTOT * DD];
__device__ float g_P [(size_t)BB * SS * SS];   // scores / probs (64 MB)
__device__ float g_O [MTOT * DD];              // scores @ V
__device__ float g_AT[MTOT * DD];              // LN(attn + x)
__device__ float g_H [MTOT * DD];              // LN(at + x)  (= res)
__device__ float g_H1[MTOT * DD];
__device__ float g_H2[MTOT * DD];

// ---------------- helpers ---------------------------------------------------
__device__ __forceinline__ float warp_max(float v) {
    #pragma unroll
    for (int o = 16; o > 0; o >>= 1) v = fmaxf(v, __shfl_xor_sync(0xffffffffu, v, o));
    return v;
}
__device__ __forceinline__ float warp_sum(float v) {
    #pragma unroll
    for (int o = 16; o > 0; o >>= 1) v += __shfl_xor_sync(0xffffffffu, v, o);
    return v;
}
__device__ __forceinline__ float gelu_exact(float x) {
    return 0.5f * x * (1.0f + erff(x * 0.70710678118654752f));
}

// ---------------- GEMM: C = (A @ B) * scale + bias, optional exact GELU -----
// A: [M,K] row-major. TRANSB=0: B is [K,N] row-major. TRANSB=1: B is [N,K]
// row-major (C[i,j] = sum_k A[i,k]*B[j,k]).  128x128 tile, BK=8, 256 threads,
// 8x8 per-thread microtile.  M,N multiples of 128; K multiple of 8.
template<int DOGELU, int TRANSB>
__global__ __launch_bounds__(256)
void gemm128(const float* __restrict__ A, const float* __restrict__ Bm,
             const float* __restrict__ bias, float* __restrict__ C,
             int M, int N, int K, float scale,
             size_t strideA, size_t strideB, size_t strideC)
{
    __shared__ __align__(16) float As[8][128];
    __shared__ __align__(16) float Bs[8][128];

    const int t  = threadIdx.x;
    const int tx = t & 15;        // 0..15 -> column group
    const int ty = t >> 4;        // 0..15 -> row group
    const int m0 = blockIdx.y * 128;
    const int n0 = blockIdx.x * 128;

    A  += (size_t)blockIdx.z * strideA;
    Bm += (size_t)blockIdx.z * strideB;
    C  += (size_t)blockIdx.z * strideC;

    float acc[8][8];
    #pragma unroll
    for (int i = 0; i < 8; i++)
        #pragma unroll
        for (int j = 0; j < 8; j++) acc[i][j] = 0.0f;

    // A-tile (and NT B-tile) loader indices: 128 rows x 8 k, one float4/thread
    const int lr = t >> 1;            // 0..127
    const int lk = (t & 1) * 4;       // 0 or 4
    // NN B-tile loader: 8 k-rows x 128 cols, one float4/thread
    const int bkr = t >> 5;           // 0..7
    const int bn  = (t & 31) * 4;     // 0..124

    for (int kt = 0; kt < K; kt += 8) {
        float4 av = *(const float4*)&A[(size_t)(m0 + lr) * K + kt + lk];
        As[lk + 0][lr] = av.x;  As[lk + 1][lr] = av.y;
        As[lk + 2][lr] = av.z;  As[lk + 3][lr] = av.w;

        if (TRANSB) {
            float4 bv = *(const float4*)&Bm[(size_t)(n0 + lr) * K + kt + lk];
            Bs[lk + 0][lr] = bv.x;  Bs[lk + 1][lr] = bv.y;
            Bs[lk + 2][lr] = bv.z;  Bs[lk + 3][lr] = bv.w;
        } else {
            float4 bv = *(const float4*)&Bm[(size_t)(kt + bkr) * N + n0 + bn];
            *(float4*)&Bs[bkr][bn] = bv;
        }
        __syncthreads();

        #pragma unroll
        for (int k = 0; k < 8; k++) {
            float a[8], b[8];
            *(float4*)&a[0] = *(const float4*)&As[k][ty * 4];
            *(float4*)&a[4] = *(const float4*)&As[k][64 + ty * 4];
            *(float4*)&b[0] = *(const float4*)&Bs[k][tx * 4];
            *(float4*)&b[4] = *(const float4*)&Bs[k][64 + tx * 4];
            #pragma unroll
            for (int i = 0; i < 8; i++)
                #pragma unroll
                for (int j = 0; j < 8; j++)
                    acc[i][j] = fmaf(a[i], b[j], acc[i][j]);
        }
        __syncthreads();
    }

    // epilogue
    float bvals[8];
    if (bias) {
        *(float4*)&bvals[0] = *(const float4*)&bias[n0 + tx * 4];
        *(float4*)&bvals[4] = *(const float4*)&bias[n0 + 64 + tx * 4];
    } else {
        #pragma unroll
        for (int j = 0; j < 8; j++) bvals[j] = 0.0f;
    }

    #pragma unroll
    for (int i = 0; i < 8; i++) {
        const int m = m0 + ((i < 4) ? (ty * 4 + i) : (64 + ty * 4 + (i - 4)));
        #pragma unroll
        for (int jh = 0; jh < 2; jh++) {
            float4 v;
            v.x = acc[i][jh * 4 + 0] * scale + bvals[jh * 4 + 0];
            v.y = acc[i][jh * 4 + 1] * scale + bvals[jh * 4 + 1];
            v.z = acc[i][jh * 4 + 2] * scale + bvals[jh * 4 + 2];
            v.w = acc[i][jh * 4 + 3] * scale + bvals[jh * 4 + 3];
            if (DOGELU) {
                v.x = gelu_exact(v.x); v.y = gelu_exact(v.y);
                v.z = gelu_exact(v.z); v.w = gelu_exact(v.w);
            }
            const int n = n0 + jh * 64 + tx * 4;
            *(float4*)&C[(size_t)m * N + n] = v;
        }
    }
}

// ---------------- row softmax over 2048 elements, in-place ------------------
__global__ __launch_bounds__(256)
void softmax2048(float* __restrict__ P)
{
    float* p = P + (size_t)blockIdx.x * 2048;
    const int t    = threadIdx.x;
    const int lane = t & 31;
    const int wid  = t >> 5;
    __shared__ float red[8];

    float4 v0 = ((const float4*)p)[t];
    float4 v1 = ((const float4*)p)[256 + t];

    float mx = fmaxf(fmaxf(fmaxf(v0.x, v0.y), fmaxf(v0.z, v0.w)),
                     fmaxf(fmaxf(v1.x, v1.y), fmaxf(v1.z, v1.w)));
    mx = warp_max(mx);
    if (lane == 0) red[wid] = mx;
    __syncthreads();
    mx = red[0];
    #pragma unroll
    for (int i = 1; i < 8; i++) mx = fmaxf(mx, red[i]);
    __syncthreads();

    v0.x = expf(v0.x - mx); v0.y = expf(v0.y - mx);
    v0.z = expf(v0.z - mx); v0.w = expf(v0.w - mx);
    v1.x = expf(v1.x - mx); v1.y = expf(v1.y - mx);
    v1.z = expf(v1.z - mx); v1.w = expf(v1.w - mx);

    float s = (v0.x + v0.y + v0.z + v0.w) + (v1.x + v1.y + v1.z + v1.w);
    s = warp_sum(s);
    if (lane == 0) red[wid] = s;
    __syncthreads();
    s = red[0];
    #pragma unroll
    for (int i = 1; i < 8; i++) s += red[i];

    const float inv = 1.0f / s;
    v0.x *= inv; v0.y *= inv; v0.z *= inv; v0.w *= inv;
    v1.x *= inv; v1.y *= inv; v1.z *= inv; v1.w *= inv;
    ((float4*)p)[t]       = v0;
    ((float4*)p)[256 + t] = v1;
}

// ---------------- out = LayerNorm(A + R) * gamma + beta  (row = 1024) -------
__global__ __launch_bounds__(256)
void add_ln1024(const float* __restrict__ A, const float* __restrict__ R,
                const float* __restrict__ gamma, const float* __restrict__ beta,
                float* __restrict__ out)
{
    const size_t row = blockIdx.x;
    const int t    = threadIdx.x;
    const int lane = t & 31;
    const int wid  = t >> 5;
    __shared__ float rs[8];
    __shared__ float rq[8];

    float4 a = ((const float4*)(A + row * 1024))[t];
    float4 r = ((const float4*)(R + row * 1024))[t];
    float h0 = a.x + r.x, h1 = a.y + r.y, h2 = a.z + r.z, h3 = a.w + r.w;

    float s = h0 + h1 + h2 + h3;
    float q = h0 * h0 + h1 * h1 + h2 * h2 + h3 * h3;
    s = warp_sum(s);
    q = warp_sum(q);
    if (lane == 0) { rs[wid] = s; rq[wid] = q; }
    __syncthreads();
    s = rs[0]; q = rq[0];
    #pragma unroll
    for (int i = 1; i < 8; i++) { s += rs[i]; q += rq[i]; }

    const float mean = s * (1.0f / 1024.0f);
    const float var  = q * (1.0f / 1024.0f) - mean * mean;
    const float rstd = rsqrtf(var + LN_EPS);

    float4 gg = ((const float4*)gamma)[t];
    float4 bb = ((const float4*)beta)[t];
    float4 o;
    o.x = (h0 - mean) * rstd * gg.x + bb.x;
    o.y = (h1 - mean) * rstd * gg.y + bb.y;
    o.z = (h2 - mean) * rstd * gg.z + bb.z;
    o.w = (h3 - mean) * rstd * gg.w + bb.w;
    ((float4*)(out + row * 1024))[t] = o;
}

// ---------------- launcher ---------------------------------------------------
extern "C" void kernel_launch(void* const* d_in, const int* in_sizes, int n_in,
                              void* d_out, int out_size)
{
    const float* x    = (const float*)d_in[0];
    const float* Wq   = (const float*)d_in[1];
    const float* bq   = (const float*)d_in[2];
    const float* Wk   = (const float*)d_in[3];
    const float* bk   = (const float*)d_in[4];
    const float* Wv   = (const float*)d_in[5];
    const float* bv   = (const float*)d_in[6];
    const float* gat  = (const float*)d_in[7];
    const float* bat  = (const float*)d_in[8];
    const float* gln  = (const float*)d_in[9];
    const float* bln  = (const float*)d_in[10];
    const float* W1   = (const float*)d_in[11];
    const float* c1   = (const float*)d_in[12];
    const float* W2   = (const float*)d_in[13];
    const float* c2   = (const float*)d_in[14];
    float* out = (float*)d_out;

    float *Q, *K, *V, *P, *O, *AT, *H, *H1, *H2;
    cudaGetSymbolAddress((void**)&Q,  g_Q);
    cudaGetSymbolAddress((void**)&K,  g_K);
    cudaGetSymbolAddress((void**)&V,  g_V);
    cudaGetSymbolAddress((void**)&P,  g_P);
    cudaGetSymbolAddress((void**)&O,  g_O);
    cudaGetSymbolAddress((void**)&AT, g_AT);
    cudaGetSymbolAddress((void**)&H,  g_H);
    cudaGetSymbolAddress((void**)&H1, g_H1);
    cudaGetSymbolAddress((void**)&H2, g_H2);

    const dim3 blk(256);
    const dim3 gQKV(DD / 128, MTOT / 128, 1);        // (8, 64)
    const dim3 gSC (SS / 128, SS / 128, BB);         // (16, 16, 4)
    const dim3 gPV (DD / 128, SS / 128, BB);         // (8, 16, 4)

    const size_t sSD = (size_t)SS * DD;   // per-batch stride for Q/K/V/O
    const size_t sSS = (size_t)SS * SS;   // per-batch stride for scores

    // Q, K, V projections
    gemm128<0,0><<<gQKV, blk>>>(x, Wq, bq, Q, MTOT, DD, DD, 1.0f, 0, 0, 0);
    gemm128<0,0><<<gQKV, blk>>>(x, Wk, bk, K, MTOT, DD, DD, 1.0f, 0, 0, 0);
    gemm128<0,0><<<gQKV, blk>>>(x, Wv, bv, V, MTOT, DD, DD, 1.0f, 0, 0, 0);

    // scores = (Q @ K^T) / 8, batched
    gemm128<0,1><<<gSC, blk>>>(Q, K, nullptr, P, SS, SS, DD, INV_SCALE, sSD, sSD, sSS);

    // row softmax (in-place)
    softmax2048<<<BB * SS, blk>>>(P);

    // O = P @ V, batched
    gemm128<0,0><<<gPV, blk>>>(P, V, nullptr, O, SS, DD, SS, 1.0f, sSS, sSD, sSD);

    // at = LN(O + x); h = LN(at + x)
    add_ln1024<<<MTOT, blk>>>(O,  x, gat, bat, AT);
    add_ln1024<<<MTOT, blk>>>(AT, x, gln, bln, H);

    // FFN: gelu(h@W1+c1), gelu(...@W2+c2)
    gemm128<1,0><<<gQKV, blk>>>(H,  W1, c1, H1, MTOT, DD, DD, 1.0f, 0, 0, 0);
    gemm128<1,0><<<gQKV, blk>>>(H1, W2, c2, H2, MTOT, DD, DD, 1.0f, 0, 0, 0);

    // out = LN(h2 + h)
    add_ln1024<<<MTOT, blk>>>(H2, H, gln, bln, out);
}

// round 3
// speedup vs baseline: 3.5560x; 3.5560x over previous
#include <cuda_runtime.h>
#include <cstdint>
#include <math.h>
#include <stddef.h>

// Problem constants
#define BB 4
#define SS 2048
#define DD 1024
#define MTOT (BB * SS)          // 8192
#define LN_EPS 1e-5f
#define INV_SCALE 0.125f        // 1/sqrt(64)

// ---------------- scratch (device globals; no allocation allowed) ----------
__device__ float g_xr [MTOT * DD];             // round(x)
__device__ float g_WqT[DD * DD];
__device__ float g_WkT[DD * DD];
__device__ float g_WvT[DD * DD];
__device__ float g_W1T[DD * DD];
__device__ float g_W2T[DD * DD];
__device__ float g_Q  [MTOT * DD];             // rounded
__device__ float g_K  [MTOT * DD];             // rounded
__device__ float g_V  [MTOT * DD];
__device__ float g_VT [MTOT * DD];             // per-batch [D,S], rounded
__device__ float g_P  [(size_t)BB * SS * SS];  // scores / probs (64 MB)
__device__ float g_O  [MTOT * DD];
__device__ float g_AT [MTOT * DD];
__device__ float g_H  [MTOT * DD];
__device__ float g_Hr [MTOT * DD];             // rounded copy of H
__device__ float g_H1 [MTOT * DD];             // rounded
__device__ float g_H2 [MTOT * DD];

// ---------------- helpers ---------------------------------------------------
__device__ __forceinline__ uint32_t smem_u32(const void* p) {
    uint32_t a;
    asm("{ .reg .u64 t; cvta.to.shared.u64 t, %1; cvt.u32.u64 %0, t; }" : "=r"(a) : "l"(p));
    return a;
}
__device__ __forceinline__ float to_tf32(float x) {
    float r;
    asm("cvt.rna.tf32.f32 %0, %1;" : "=f"(r) : "f"(x));
    return r;
}
__device__ __forceinline__ void cpa16(uint32_t dst, const void* src) {
    asm volatile("cp.async.cg.shared.global [%0], [%1], 16;" :: "r"(dst), "l"(src));
}
#define CP_COMMIT() asm volatile("cp.async.commit_group;" ::: "memory")
#define CP_WAIT2()  asm volatile("cp.async.wait_group 2;" ::: "memory")

__device__ __forceinline__ float gelu_exact(float x) {
    return 0.5f * x * (1.0f + erff(x * 0.70710678118654752f));
}
__device__ __forceinline__ float warp_max(float v) {
    #pragma unroll
    for (int o = 16; o > 0; o >>= 1) v = fmaxf(v, __shfl_xor_sync(0xffffffffu, v, o));
    return v;
}
__device__ __forceinline__ float warp_sum(float v) {
    #pragma unroll
    for (int o = 16; o > 0; o >>= 1) v += __shfl_xor_sync(0xffffffffu, v, o);
    return v;
}

// mma.sync m16n8k8 tf32 (baseline PTX, no 'a'-arch feature needed)
__device__ __forceinline__ void mma_tf32(float* d, const uint32_t* a, const uint32_t* b) {
    asm volatile(
        "mma.sync.aligned.m16n8k8.row.col.f32.tf32.tf32.f32 "
        "{%0,%1,%2,%3}, {%4,%5,%6,%7}, {%8,%9}, {%0,%1,%2,%3};"
        : "+f"(d[0]), "+f"(d[1]), "+f"(d[2]), "+f"(d[3])
        : "r"(a[0]), "r"(a[1]), "r"(a[2]), "r"(a[3]), "r"(b[0]), "r"(b[1]));
}

// ---------------- tf32 tensor GEMM ------------------------------------------
// C[M,N] = A[M,K] @ B^T, B stored [N,K] row-major (both K-major).
// CTA tile 128x256, warp tile 64x64 (8 warps), BK=32, 3-stage cp.async.
static constexpr int STAGE_BYTES = (128 + 256) * 32 * 4;        // 49152
static constexpr int SMEM_BYTES  = 3 * STAGE_BYTES;             // 147456

// swizzled byte offset within a tile of 128B rows
#define SWA(row, colf) ((row) * 128 + (((colf) * 4) ^ (((row) & 7) << 4)))

template<int DOGELU, int ROUND>
__global__ __launch_bounds__(256)
void tgemm(const float* __restrict__ A, const float* __restrict__ B,
           const float* __restrict__ bias, float* __restrict__ C,
           int ldA, int ldB, int ldC, int K, float scale,
           size_t strA, size_t strB, size_t strC)
{
    extern __shared__ __align__(1024) char smem[];
    const uint32_t sb = smem_u32(smem);
    const int tid  = threadIdx.x;
    const int lane = tid & 31;
    const int wid  = tid >> 5;
    const int warpRow = (wid & 1) * 64;    // 2 m-groups of 64
    const int warpCol = (wid >> 1) * 64;   // 4 n-groups of 64

    const int m0 = blockIdx.y * 128;
    const int n0 = blockIdx.x * 256;
    A += (size_t)blockIdx.z * strA + (size_t)m0 * ldA;
    B += (size_t)blockIdx.z * strB + (size_t)n0 * ldB;
    C += (size_t)blockIdx.z * strC;

    float acc[4][8][4];
    #pragma unroll
    for (int i = 0; i < 4; i++)
        #pragma unroll
        for (int j = 0; j < 8; j++)
            #pragma unroll
            for (int q = 0; q < 4; q++) acc[i][j][q] = 0.0f;

    const int NK = K >> 5;

    // per-thread loader indices (row = idx>>3, kseg = idx&7; 16B each)
    const int arow0 = tid >> 3;           // A: 4 iters of 256 -> rows 0..127
    const int aks   = (tid & 7);

    // ---- stage loader ----
    auto load_stage = [&](int kt, int st) {
        const int koff = kt * 32;
        const uint32_t stb = sb + st * STAGE_BYTES;
        #pragma unroll
        for (int i = 0; i < 4; i++) {
            const int row = arow0 + i * 32;
            cpa16(stb + SWA(row, aks * 4),
                  A + (size_t)row * ldA + koff + aks * 4);
        }
        const uint32_t stbB = stb + 16384;
        #pragma unroll
        for (int i = 0; i < 8; i++) {
            const int row = arow0 + i * 32;
            cpa16(stbB + SWA(row, aks * 4),
                  B + (size_t)row * ldB + koff + aks * 4);
        }
        CP_COMMIT();
    };

    load_stage(0, 0);
    if (NK > 1) load_stage(1, 1);
    if (NK > 2) load_stage(2, 2);

    const int r_lo = lane >> 2;
    const int c_lo = lane & 3;

    for (int kt = 0; kt < NK; kt++) {
        CP_WAIT2();
        __syncthreads();

        const uint32_t stb  = sb + (kt % 3) * STAGE_BYTES;
        const uint32_t stbB = stb + 16384;
        const char* smA = (const char*)smem + (kt % 3) * STAGE_BYTES;
        const char* smB = smA + 16384;

        #pragma unroll
        for (int kk = 0; kk < 4; kk++) {
            const int k0 = kk * 8;
            const int ca = k0 + c_lo;

            uint32_t afr[4][4];
            #pragma unroll
            for (int ma = 0; ma < 4; ma++) {
                const int r  = warpRow + ma * 16 + r_lo;
                const int r2 = r + 8;
                afr[ma][0] = *(const uint32_t*)(smA + SWA(r,  ca));
                afr[ma][1] = *(const uint32_t*)(smA + SWA(r2, ca));
                afr[ma][2] = *(const uint32_t*)(smA + SWA(r,  ca + 4));
                afr[ma][3] = *(const uint32_t*)(smA + SWA(r2, ca + 4));
            }
            uint32_t bfr[8][2];
            #pragma unroll
            for (int nb = 0; nb < 8; nb++) {
                const int n = warpCol + nb * 8 + r_lo;
                bfr[nb][0] = *(const uint32_t*)(smB + SWA(n, ca));
                bfr[nb][1] = *(const uint32_t*)(smB + SWA(n, ca + 4));
            }
            #pragma unroll
            for (int ma = 0; ma < 4; ma++)
                #pragma unroll
                for (int nb = 0; nb < 8; nb++)
                    mma_tf32(acc[ma][nb], afr[ma], bfr[nb]);
        }
        __syncthreads();

        if (kt + 3 < NK) load_stage(kt + 3, kt % 3);
    }

    // ---- epilogue: registers -> gmem ----
    #pragma unroll
    for (int ma = 0; ma < 4; ma++) {
        const int r0 = m0 + warpRow + ma * 16 + r_lo;
        const int r1 = r0 + 8;
        #pragma unroll
        for (int nb = 0; nb < 8; nb++) {
            const int col = n0 + warpCol + nb * 8 + c_lo * 2;
            float b0 = 0.0f, b1 = 0.0f;
            if (bias) {
                float2 bv = *(const float2*)&bias[col];
                b0 = bv.x; b1 = bv.y;
            }
            float v0 = acc[ma][nb][0] * scale + b0;
            float v1 = acc[ma][nb][1] * scale + b1;
            float v2 = acc[ma][nb][2] * scale + b0;
            float v3 = acc[ma][nb][3] * scale + b1;
            if (DOGELU) {
                v0 = gelu_exact(v0); v1 = gelu_exact(v1);
                v2 = gelu_exact(v2); v3 = gelu_exact(v3);
            }
            if (ROUND) {
                v0 = to_tf32(v0); v1 = to_tf32(v1);
                v2 = to_tf32(v2); v3 = to_tf32(v3);
            }
            *(float2*)&C[(size_t)r0 * ldC + col] = make_float2(v0, v1);
            *(float2*)&C[(size_t)r1 * ldC + col] = make_float2(v2, v3);
        }
    }
}

// ---------------- elementwise / reduction kernels ---------------------------
__global__ __launch_bounds__(256)
void round_copy(const float* __restrict__ in, float* __restrict__ out, size_t n4)
{
    size_t i = (size_t)blockIdx.x * blockDim.x + threadIdx.x;
    if (i < n4) {
        float4 v = ((const float4*)in)[i];
        v.x = to_tf32(v.x); v.y = to_tf32(v.y);
        v.z = to_tf32(v.z); v.w = to_tf32(v.w);
        ((float4*)out)[i] = v;
    }
}

// out[c, r] = round(in[r, c]); block (32, 8), tiles 32x32
__global__ __launch_bounds__(256)
void transpose_round(const float* __restrict__ in, float* __restrict__ out,
                     int rows, int cols, size_t sIn, size_t sOut)
{
    __shared__ float tile[32][33];
    in  += (size_t)blockIdx.z * sIn;
    out += (size_t)blockIdx.z * sOut;
    const int c0 = blockIdx.x * 32, r0 = blockIdx.y * 32;
    #pragma unroll
    for (int i = 0; i < 4; i++)
        tile[threadIdx.y + i * 8][threadIdx.x] =
            in[(size_t)(r0 + threadIdx.y + i * 8) * cols + c0 + threadIdx.x];
    __syncthreads();
    #pragma unroll
    for (int i = 0; i < 4; i++)
        out[(size_t)(c0 + threadIdx.y + i * 8) * rows + r0 + threadIdx.x] =
            to_tf32(tile[threadIdx.x][threadIdx.y + i * 8]);
}

__global__ __launch_bounds__(256)
void softmax2048(float* __restrict__ P)
{
    float* p = P + (size_t)blockIdx.x * 2048;
    const int t = threadIdx.x, lane = t & 31, wid = t >> 5;
    __shared__ float red[8];

    float4 v0 = ((const float4*)p)[t];
    float4 v1 = ((const float4*)p)[256 + t];

    float mx = fmaxf(fmaxf(fmaxf(v0.x, v0.y), fmaxf(v0.z, v0.w)),
                     fmaxf(fmaxf(v1.x, v1.y), fmaxf(v1.z, v1.w)));
    mx = warp_max(mx);
    if (lane == 0) red[wid] = mx;
    __syncthreads();
    mx = red[0];
    #pragma unroll
    for (int i = 1; i < 8; i++) mx = fmaxf(mx, red[i]);
    __syncthreads();

    v0.x = expf(v0.x - mx); v0.y = expf(v0.y - mx);
    v0.z = expf(v0.z - mx); v0.w = expf(v0.w - mx);
    v1.x = expf(v1.x - mx); v1.y = expf(v1.y - mx);
    v1.z = expf(v1.z - mx); v1.w = expf(v1.w - mx);

    float s = (v0.x + v0.y + v0.z + v0.w) + (v1.x + v1.y + v1.z + v1.w);
    s = warp_sum(s);
    if (lane == 0) red[wid] = s;
    __syncthreads();
    s = red[0];
    #pragma unroll
    for (int i = 1; i < 8; i++) s += red[i];

    const float inv = 1.0f / s;
    v0.x = to_tf32(v0.x * inv); v0.y = to_tf32(v0.y * inv);
    v0.z = to_tf32(v0.z * inv); v0.w = to_tf32(v0.w * inv);
    v1.x = to_tf32(v1.x * inv); v1.y = to_tf32(v1.y * inv);
    v1.z = to_tf32(v1.z * inv); v1.w = to_tf32(v1.w * inv);
    ((float4*)p)[t]       = v0;
    ((float4*)p)[256 + t] = v1;
}

template<int DUAL>
__global__ __launch_bounds__(256)
void add_ln1024(const float* __restrict__ A, const float* __restrict__ R,
                const float* __restrict__ gamma, const float* __restrict__ beta,
                float* __restrict__ out, float* __restrict__ out_r)
{
    const size_t row = blockIdx.x;
    const int t = threadIdx.x, lane = t & 31, wid = t >> 5;
    __shared__ float rs[8], rq[8];

    float4 a = ((const float4*)(A + row * 1024))[t];
    float4 r = ((const float4*)(R + row * 1024))[t];
    float h0 = a.x + r.x, h1 = a.y + r.y, h2 = a.z + r.z, h3 = a.w + r.w;

    float s = h0 + h1 + h2 + h3;
    float q = h0 * h0 + h1 * h1 + h2 * h2 + h3 * h3;
    s = warp_sum(s);
    q = warp_sum(q);
    if (lane == 0) { rs[wid] = s; rq[wid] = q; }
    __syncthreads();
    s = rs[0]; q = rq[0];
    #pragma unroll
    for (int i = 1; i < 8; i++) { s += rs[i]; q += rq[i]; }

    const float mean = s * (1.0f / 1024.0f);
    const float var  = q * (1.0f / 1024.0f) - mean * mean;
    const float rstd = rsqrtf(var + LN_EPS);

    float4 gg = ((const float4*)gamma)[t];
    float4 bb = ((const float4*)beta)[t];
    float4 o;
    o.x = (h0 - mean) * rstd * gg.x + bb.x;
    o.y = (h1 - mean) * rstd * gg.y + bb.y;
    o.z = (h2 - mean) * rstd * gg.z + bb.z;
    o.w = (h3 - mean) * rstd * gg.w + bb.w;
    ((float4*)(out + row * 1024))[t] = o;
    if (DUAL) {
        float4 o2;
        o2.x = to_tf32(o.x); o2.y = to_tf32(o.y);
        o2.z = to_tf32(o.z); o2.w = to_tf32(o.w);
        ((float4*)(out_r + row * 1024))[t] = o2;
    }
}

// ---------------- launcher ---------------------------------------------------
extern "C" void kernel_launch(void* const* d_in, const int* in_sizes, int n_in,
                              void* d_out, int out_size)
{
    const float* x   = (const float*)d_in[0];
    const float* Wq  = (const float*)d_in[1];
    const float* bq  = (const float*)d_in[2];
    const float* Wk  = (const float*)d_in[3];
    const float* bk  = (const float*)d_in[4];
    const float* Wv  = (const float*)d_in[5];
    const float* bv  = (const float*)d_in[6];
    const float* gat = (const float*)d_in[7];
    const float* bat = (const float*)d_in[8];
    const float* gln = (const float*)d_in[9];
    const float* bln = (const float*)d_in[10];
    const float* W1  = (const float*)d_in[11];
    const float* c1  = (const float*)d_in[12];
    const float* W2  = (const float*)d_in[13];
    const float* c2  = (const float*)d_in[14];
    float* out = (float*)d_out;

    float *xr, *WqT, *WkT, *WvT, *W1T, *W2T, *Q, *K, *V, *VT, *P, *O, *AT, *H, *Hr, *H1, *H2;
    cudaGetSymbolAddress((void**)&xr,  g_xr);
    cudaGetSymbolAddress((void**)&WqT, g_WqT);
    cudaGetSymbolAddress((void**)&WkT, g_WkT);
    cudaGetSymbolAddress((void**)&WvT, g_WvT);
    cudaGetSymbolAddress((void**)&W1T, g_W1T);
    cudaGetSymbolAddress((void**)&W2T, g_W2T);
    cudaGetSymbolAddress((void**)&Q,   g_Q);
    cudaGetSymbolAddress((void**)&K,   g_K);
    cudaGetSymbolAddress((void**)&V,   g_V);
    cudaGetSymbolAddress((void**)&VT,  g_VT);
    cudaGetSymbolAddress((void**)&P,   g_P);
    cudaGetSymbolAddress((void**)&O,   g_O);
    cudaGetSymbolAddress((void**)&AT,  g_AT);
    cudaGetSymbolAddress((void**)&H,   g_H);
    cudaGetSymbolAddress((void**)&Hr,  g_Hr);
    cudaGetSymbolAddress((void**)&H1,  g_H1);
    cudaGetSymbolAddress((void**)&H2,  g_H2);

    cudaFuncSetAttribute(tgemm<0,0>, cudaFuncAttributeMaxDynamicSharedMemorySize, SMEM_BYTES);
    cudaFuncSetAttribute(tgemm<0,1>, cudaFuncAttributeMaxDynamicSharedMemorySize, SMEM_BYTES);
    cudaFuncSetAttribute(tgemm<1,0>, cudaFuncAttributeMaxDynamicSharedMemorySize, SMEM_BYTES);
    cudaFuncSetAttribute(tgemm<1,1>, cudaFuncAttributeMaxDynamicSharedMemorySize, SMEM_BYTES);

    const dim3 blk(256);
    const size_t sSD = (size_t)SS * DD;
    const size_t sSS = (size_t)SS * SS;

    // operand preparation (all MMA inputs pre-rounded to tf32, RN)
    round_copy<<<(MTOT * DD / 4 + 255) / 256, blk>>>(x, xr, (size_t)MTOT * DD / 4);
    {
        const dim3 gT(32, 32, 1);
        const dim3 bT(32, 8);
        transpose_round<<<gT, bT>>>(Wq, WqT, DD, DD, 0, 0);
        transpose_round<<<gT, bT>>>(Wk, WkT, DD, DD, 0, 0);
        transpose_round<<<gT, bT>>>(Wv, WvT, DD, DD, 0, 0);
        transpose_round<<<gT, bT>>>(W1, W1T, DD, DD, 0, 0);
        transpose_round<<<gT, bT>>>(W2, W2T, DD, DD, 0, 0);
    }

    const dim3 gQKV(DD / 256, MTOT / 128, 1);      // (4, 64)
    const dim3 gSC (SS / 256, SS / 128, BB);       // (8, 16, 4)
    const dim3 gPV (DD / 256, SS / 128, BB);       // (4, 16, 4)

    // QKV projections (Q,K rounded in epilogue; V rounded during transpose)
    tgemm<0,1><<<gQKV, blk, SMEM_BYTES>>>(xr, WqT, bq, Q, DD, DD, DD, DD, 1.0f, 0, 0, 0);
    tgemm<0,1><<<gQKV, blk, SMEM_BYTES>>>(xr, WkT, bk, K, DD, DD, DD, DD, 1.0f, 0, 0, 0);
    tgemm<0,0><<<gQKV, blk, SMEM_BYTES>>>(xr, WvT, bv, V, DD, DD, DD, DD, 1.0f, 0, 0, 0);

    // V^T per batch: [S,D] -> [D,S], rounded
    transpose_round<<<dim3(DD / 32, SS / 32, BB), dim3(32, 8)>>>(V, VT, SS, DD, sSD, sSD);

    // scores = (Q @ K^T) / 8
    tgemm<0,0><<<gSC, blk, SMEM_BYTES>>>(Q, K, nullptr, P, DD, DD, SS, DD, INV_SCALE, sSD, sSD, sSS);

    // softmax (rounds P to tf32 at store)
    softmax2048<<<BB * SS, blk>>>(P);

    // O = P @ V  (B = V^T stored [D,S])
    tgemm<0,0><<<gPV, blk, SMEM_BYTES>>>(P, VT, nullptr, O, SS, SS, DD, SS, 1.0f, sSS, sSD, sSD);

    // at = LN(O + x); h = LN(at + x) (+ rounded copy for FFN input)
    add_ln1024<0><<<MTOT, blk>>>(O,  x, gat, bat, AT, nullptr);
    add_ln1024<1><<<MTOT, blk>>>(AT, x, gln, bln, H, Hr);

    // FFN
    tgemm<1,1><<<gQKV, blk, SMEM_BYTES>>>(Hr, W1T, c1, H1, DD, DD, DD, DD, 1.0f, 0, 0, 0);
    tgemm<1,0><<<gQKV, blk, SMEM_BYTES>>>(H1, W2T, c2, H2, DD, DD, DD, DD, 1.0f, 0, 0, 0);

    // out = LN(h2 + h)
    add_ln1024<0><<<MTOT, blk>>>(H2, H, gln, bln, out, nullptr);
}

// round 4
// speedup vs baseline: 3.5769x; 1.0059x over previous
#include <cuda_runtime.h>
#include <cstdint>
#include <math.h>
#include <stddef.h>

// Problem constants
#define BB 4
#define SS 2048
#define DD 1024
#define MTOT (BB * SS)          // 8192
#define LN_EPS 1e-5f
#define INV_SCALE 0.125f        // 1/sqrt(64)

// ---------------- scratch (device globals; no allocation allowed) ----------
__device__ float g_xr [MTOT * DD];             // round(x)
__device__ float g_WqT[DD * DD];
__device__ float g_WkT[DD * DD];
__device__ float g_WvT[DD * DD];
__device__ float g_W1T[DD * DD];
__device__ float g_W2T[DD * DD];
__device__ float g_Q  [MTOT * DD];             // rounded
__device__ float g_K  [MTOT * DD];             // rounded
__device__ float g_V  [MTOT * DD];
__device__ float g_VT [MTOT * DD];             // per-batch [D,S], rounded
__device__ float g_P  [(size_t)BB * SS * SS];  // scores / probs (64 MB)
__device__ float g_O  [MTOT * DD];
__device__ float g_H  [MTOT * DD];
__device__ float g_Hr [MTOT * DD];             // rounded copy of H
__device__ float g_H1 [MTOT * DD];             // rounded
__device__ float g_H2 [MTOT * DD];

// ---------------- helpers ---------------------------------------------------
__device__ __forceinline__ uint32_t smem_u32(const void* p) {
    uint32_t a;
    asm("{ .reg .u64 t; cvta.to.shared.u64 t, %1; cvt.u32.u64 %0, t; }" : "=r"(a) : "l"(p));
    return a;
}
__device__ __forceinline__ float to_tf32(float x) {
    float r;
    asm("cvt.rna.tf32.f32 %0, %1;" : "=f"(r) : "f"(x));
    return r;
}
__device__ __forceinline__ void cpa16(uint32_t dst, const void* src) {
    asm volatile("cp.async.cg.shared.global [%0], [%1], 16;" :: "r"(dst), "l"(src));
}
#define CP_COMMIT() asm volatile("cp.async.commit_group;" ::: "memory")
#define CP_WAIT2()  asm volatile("cp.async.wait_group 2;" ::: "memory")

__device__ __forceinline__ float gelu_exact(float x) {
    return 0.5f * x * (1.0f + erff(x * 0.70710678118654752f));
}
__device__ __forceinline__ float warp_max(float v) {
    #pragma unroll
    for (int o = 16; o > 0; o >>= 1) v = fmaxf(v, __shfl_xor_sync(0xffffffffu, v, o));
    return v;
}
__device__ __forceinline__ float warp_sum(float v) {
    #pragma unroll
    for (int o = 16; o > 0; o >>= 1) v += __shfl_xor_sync(0xffffffffu, v, o);
    return v;
}

// mma.sync m16n8k8 tf32 (baseline PTX)
__device__ __forceinline__ void mma_tf32(float* d, const uint32_t* a, const uint32_t* b) {
    asm volatile(
        "mma.sync.aligned.m16n8k8.row.col.f32.tf32.tf32.f32 "
        "{%0,%1,%2,%3}, {%4,%5,%6,%7}, {%8,%9}, {%0,%1,%2,%3};"
        : "+f"(d[0]), "+f"(d[1]), "+f"(d[2]), "+f"(d[3])
        : "r"(a[0]), "r"(a[1]), "r"(a[2]), "r"(a[3]), "r"(b[0]), "r"(b[1]));
}
// ldmatrix x4 (b16 granularity; works for 32-bit elements as 8x4 f32 tiles)
__device__ __forceinline__ void ldsm4(uint32_t* r, uint32_t addr) {
    asm volatile("ldmatrix.sync.aligned.m8n8.x4.shared.b16 {%0,%1,%2,%3}, [%4];"
        : "=r"(r[0]), "=r"(r[1]), "=r"(r[2]), "=r"(r[3]) : "r"(addr));
}

// ---------------- tf32 tensor GEMM ------------------------------------------
// C[M,N] = A[M,K] @ B^T, B stored [N,K] row-major (both K-major).
// CTA tile 128x256, warp tile 64x64 (8 warps), BK=32, 3-stage cp.async.
static constexpr int STAGE_BYTES = (128 + 256) * 32 * 4;        // 49152
static constexpr int SMEM_BYTES  = 3 * STAGE_BYTES;             // 147456

// swizzled byte offset within a tile of 128B rows
#define SWA(row, colf) ((row) * 128 + ((((colf) * 4) ^ (((row) & 7) << 4))))

template<int DOGELU, int ROUND>
__global__ __launch_bounds__(256)
void tgemm(const float* __restrict__ A, const float* __restrict__ B,
           const float* __restrict__ bias, float* __restrict__ C,
           int ldA, int ldB, int ldC, int K, float scale,
           size_t strA, size_t strB, size_t strC)
{
    extern __shared__ __align__(1024) char smem[];
    const uint32_t sb = smem_u32(smem);
    const int tid  = threadIdx.x;
    const int lane = tid & 31;
    const int wid  = tid >> 5;
    const int warpRow = (wid & 1) * 64;    // 2 m-groups of 64
    const int warpCol = (wid >> 1) * 64;   // 4 n-groups of 64

    const int m0 = blockIdx.y * 128;
    const int n0 = blockIdx.x * 256;
    A += (size_t)blockIdx.z * strA + (size_t)m0 * ldA;
    B += (size_t)blockIdx.z * strB + (size_t)n0 * ldB;
    C += (size_t)blockIdx.z * strC;

    float acc[4][8][4];
    #pragma unroll
    for (int i = 0; i < 4; i++)
        #pragma unroll
        for (int j = 0; j < 8; j++)
            #pragma unroll
            for (int q = 0; q < 4; q++) acc[i][j][q] = 0.0f;

    const int NK = K >> 5;

    // loader indices (row = idx>>3, 16B segment = idx&7)
    const int arow0 = tid >> 3;
    const int aks   = (tid & 7);

    auto load_stage = [&](int kt, int st) {
        const int koff = kt * 32;
        const uint32_t stb = sb + st * STAGE_BYTES;
        #pragma unroll
        for (int i = 0; i < 4; i++) {
            const int row = arow0 + i * 32;
            cpa16(stb + SWA(row, aks * 4),
                  A + (size_t)row * ldA + koff + aks * 4);
        }
        const uint32_t stbB = stb + 16384;
        #pragma unroll
        for (int i = 0; i < 8; i++) {
            const int row = arow0 + i * 32;
            cpa16(stbB + SWA(row, aks * 4),
                  B + (size_t)row * ldB + koff + aks * 4);
        }
        CP_COMMIT();
    };

    load_stage(0, 0);
    if (NK > 1) load_stage(1, 1);
    if (NK > 2) load_stage(2, 2);

    // ---- precomputed per-lane ldmatrix base offsets (stage-relative) ----
    // A submatrix order: m0=(r0-7,c0-3) m1=(r8-15,c0-3) m2=(r0-7,c4-7) m3=(r8-15,c4-7)
    const int sub = lane >> 3;
    const int l7  = lane & 7;
    uint32_t aoff[4], boff[4];
    {
        const int arow = l7 + (sub & 1) * 8;
        const int acol = (sub >> 1) * 4;
        #pragma unroll
        for (int ma = 0; ma < 4; ma++) {
            const int r = warpRow + ma * 16 + arow;
            aoff[ma] = SWA(r, acol);
        }
        // B: m0=(n0-7,k0-3) m1=(n0-7,k4-7) m2=(n8-15,k0-3) m3=(n8-15,k4-7)
        const int brow = l7 + (sub >> 1) * 8;
        const int bcol = (sub & 1) * 4;
        #pragma unroll
        for (int p = 0; p < 4; p++) {
            const int r = warpCol + p * 16 + brow;
            boff[p] = SWA(r, bcol);
        }
    }

    for (int kt = 0; kt < NK; kt++) {
        CP_WAIT2();
        __syncthreads();

        const uint32_t stbA = sb + (kt % 3) * STAGE_BYTES;
        const uint32_t stbB = stbA + 16384;

        #pragma unroll
        for (int kk = 0; kk < 4; kk++) {
            const uint32_t kx = kk * 32;   // byte XOR for this k-step

            uint32_t af[4][4];
            #pragma unroll
            for (int ma = 0; ma < 4; ma++)
                ldsm4(af[ma], stbA + (aoff[ma] ^ kx));
            uint32_t bf[4][4];
            #pragma unroll
            for (int p = 0; p < 4; p++)
                ldsm4(bf[p], stbB + (boff[p] ^ kx));

            #pragma unroll
            for (int ma = 0; ma < 4; ma++)
                #pragma unroll
                for (int nb = 0; nb < 8; nb++)
                    mma_tf32(acc[ma][nb], af[ma], &bf[nb >> 1][(nb & 1) * 2]);
        }
        __syncthreads();

        if (kt + 3 < NK) load_stage(kt + 3, kt % 3);
    }

    // ---- epilogue ----
    const int r_lo = lane >> 2;
    const int c_lo = lane & 3;
    #pragma unroll
    for (int ma = 0; ma < 4; ma++) {
        const int r0 = m0 + warpRow + ma * 16 + r_lo;
        const int r1 = r0 + 8;
        #pragma unroll
        for (int nb = 0; nb < 8; nb++) {
            const int col = n0 + warpCol + nb * 8 + c_lo * 2;
            float b0 = 0.0f, b1 = 0.0f;
            if (bias) {
                float2 bv = *(const float2*)&bias[col];
                b0 = bv.x; b1 = bv.y;
            }
            float v0 = acc[ma][nb][0] * scale + b0;
            float v1 = acc[ma][nb][1] * scale + b1;
            float v2 = acc[ma][nb][2] * scale + b0;
            float v3 = acc[ma][nb][3] * scale + b1;
            if (DOGELU) {
                v0 = gelu_exact(v0); v1 = gelu_exact(v1);
                v2 = gelu_exact(v2); v3 = gelu_exact(v3);
            }
            if (ROUND) {
                v0 = to_tf32(v0); v1 = to_tf32(v1);
                v2 = to_tf32(v2); v3 = to_tf32(v3);
            }
            *(float2*)&C[(size_t)r0 * ldC + col] = make_float2(v0, v1);
            *(float2*)&C[(size_t)r1 * ldC + col] = make_float2(v2, v3);
        }
    }
}

// ---------------- elementwise / reduction kernels ---------------------------
__global__ __launch_bounds__(256)
void round_copy(const float* __restrict__ in, float* __restrict__ out, size_t n4)
{
    size_t i = (size_t)blockIdx.x * blockDim.x + threadIdx.x;
    if (i < n4) {
        float4 v = ((const float4*)in)[i];
        v.x = to_tf32(v.x); v.y = to_tf32(v.y);
        v.z = to_tf32(v.z); v.w = to_tf32(v.w);
        ((float4*)out)[i] = v;
    }
}

// transpose+round for the five 1024x1024 weights in one launch (z selects)
__global__ __launch_bounds__(256)
void transpose5(const float* __restrict__ s0, const float* __restrict__ s1,
                const float* __restrict__ s2, const float* __restrict__ s3,
                const float* __restrict__ s4,
                float* __restrict__ d0, float* __restrict__ d1,
                float* __restrict__ d2, float* __restrict__ d3,
                float* __restrict__ d4)
{
    __shared__ float tile[32][33];
    const int z = blockIdx.z;
    const float* in = (z == 0) ? s0 : (z == 1) ? s1 : (z == 2) ? s2 : (z == 3) ? s3 : s4;
    float* out      = (z == 0) ? d0 : (z == 1) ? d1 : (z == 2) ? d2 : (z == 3) ? d3 : d4;
    const int c0 = blockIdx.x * 32, r0 = blockIdx.y * 32;
    #pragma unroll
    for (int i = 0; i < 4; i++)
        tile[threadIdx.y + i * 8][threadIdx.x] =
            in[(size_t)(r0 + threadIdx.y + i * 8) * DD + c0 + threadIdx.x];
    __syncthreads();
    #pragma unroll
    for (int i = 0; i < 4; i++)
        out[(size_t)(c0 + threadIdx.y + i * 8) * DD + r0 + threadIdx.x] =
            to_tf32(tile[threadIdx.x][threadIdx.y + i * 8]);
}

// out[c, r] = round(in[r, c]); per-batch, block (32, 8)
__global__ __launch_bounds__(256)
void transpose_round(const float* __restrict__ in, float* __restrict__ out,
                     int rows, int cols, size_t sIn, size_t sOut)
{
    __shared__ float tile[32][33];
    in  += (size_t)blockIdx.z * sIn;
    out += (size_t)blockIdx.z * sOut;
    const int c0 = blockIdx.x * 32, r0 = blockIdx.y * 32;
    #pragma unroll
    for (int i = 0; i < 4; i++)
        tile[threadIdx.y + i * 8][threadIdx.x] =
            in[(size_t)(r0 + threadIdx.y + i * 8) * cols + c0 + threadIdx.x];
    __syncthreads();
    #pragma unroll
    for (int i = 0; i < 4; i++)
        out[(size_t)(c0 + threadIdx.y + i * 8) * rows + r0 + threadIdx.x] =
            to_tf32(tile[threadIdx.x][threadIdx.y + i * 8]);
}

__global__ __launch_bounds__(256)
void softmax2048(float* __restrict__ P)
{
    float* p = P + (size_t)blockIdx.x * 2048;
    const int t = threadIdx.x, lane = t & 31, wid = t >> 5;
    __shared__ float red[8];

    float4 v0 = ((const float4*)p)[t];
    float4 v1 = ((const float4*)p)[256 + t];

    float mx = fmaxf(fmaxf(fmaxf(v0.x, v0.y), fmaxf(v0.z, v0.w)),
                     fmaxf(fmaxf(v1.x, v1.y), fmaxf(v1.z, v1.w)));
    mx = warp_max(mx);
    if (lane == 0) red[wid] = mx;
    __syncthreads();
    mx = red[0];
    #pragma unroll
    for (int i = 1; i < 8; i++) mx = fmaxf(mx, red[i]);
    __syncthreads();

    v0.x = expf(v0.x - mx); v0.y = expf(v0.y - mx);
    v0.z = expf(v0.z - mx); v0.w = expf(v0.w - mx);
    v1.x = expf(v1.x - mx); v1.y = expf(v1.y - mx);
    v1.z = expf(v1.z - mx); v1.w = expf(v1.w - mx);

    float s = (v0.x + v0.y + v0.z + v0.w) + (v1.x + v1.y + v1.z + v1.w);
    s = warp_sum(s);
    if (lane == 0) red[wid] = s;
    __syncthreads();
    s = red[0];
    #pragma unroll
    for (int i = 1; i < 8; i++) s += red[i];

    const float inv = 1.0f / s;
    v0.x = to_tf32(v0.x * inv); v0.y = to_tf32(v0.y * inv);
    v0.z = to_tf32(v0.z * inv); v0.w = to_tf32(v0.w * inv);
    v1.x = to_tf32(v1.x * inv); v1.y = to_tf32(v1.y * inv);
    v1.z = to_tf32(v1.z * inv); v1.w = to_tf32(v1.w * inv);
    ((float4*)p)[t]       = v0;
    ((float4*)p)[256 + t] = v1;
}

// single add+LN (used for final output)
__global__ __launch_bounds__(256)
void add_ln1024(const float* __restrict__ A, const float* __restrict__ R,
                const float* __restrict__ gamma, const float* __restrict__ beta,
                float* __restrict__ out)
{
    const size_t row = blockIdx.x;
    const int t = threadIdx.x, lane = t & 31, wid = t >> 5;
    __shared__ float rs[8], rq[8];

    float4 a = ((const float4*)(A + row * 1024))[t];
    float4 r = ((const float4*)(R + row * 1024))[t];
    float h0 = a.x + r.x, h1 = a.y + r.y, h2 = a.z + r.z, h3 = a.w + r.w;

    float s = h0 + h1 + h2 + h3;
    float q = h0 * h0 + h1 * h1 + h2 * h2 + h3 * h3;
    s = warp_sum(s); q = warp_sum(q);
    if (lane == 0) { rs[wid] = s; rq[wid] = q; }
    __syncthreads();
    s = rs[0]; q = rq[0];
    #pragma unroll
    for (int i = 1; i < 8; i++) { s += rs[i]; q += rq[i]; }

    const float mean = s * (1.0f / 1024.0f);
    const float var  = q * (1.0f / 1024.0f) - mean * mean;
    const float rstd = rsqrtf(var + LN_EPS);

    float4 gg = ((const float4*)gamma)[t];
    float4 bb = ((const float4*)beta)[t];
    float4 o;
    o.x = (h0 - mean) * rstd * gg.x + bb.x;
    o.y = (h1 - mean) * rstd * gg.y + bb.y;
    o.z = (h2 - mean) * rstd * gg.z + bb.z;
    o.w = (h3 - mean) * rstd * gg.w + bb.w;
    ((float4*)(out + row * 1024))[t] = o;
}

// fused: at = LN(O + x)*g_at+b_at;  H = LN(at + x)*g_ln+b_ln;  Hr = tf32(H)
__global__ __launch_bounds__(256)
void ln2_fused(const float* __restrict__ O, const float* __restrict__ X,
               const float* __restrict__ gat, const float* __restrict__ bat,
               const float* __restrict__ gln, const float* __restrict__ bln,
               float* __restrict__ H, float* __restrict__ Hr)
{
    const size_t row = blockIdx.x;
    const int t = threadIdx.x, lane = t & 31, wid = t >> 5;
    __shared__ float rs[8], rq[8];

    float4 a = ((const float4*)(O + row * 1024))[t];
    float4 xv = ((const float4*)(X + row * 1024))[t];
    float h[4] = {a.x + xv.x, a.y + xv.y, a.z + xv.z, a.w + xv.w};

    // --- LN 1 ---
    float s = h[0] + h[1] + h[2] + h[3];
    float q = h[0]*h[0] + h[1]*h[1] + h[2]*h[2] + h[3]*h[3];
    s = warp_sum(s); q = warp_sum(q);
    if (lane == 0) { rs[wid] = s; rq[wid] = q; }
    __syncthreads();
    s = rs[0]; q = rq[0];
    #pragma unroll
    for (int i = 1; i < 8; i++) { s += rs[i]; q += rq[i]; }
    float mean = s * (1.0f / 1024.0f);
    float var  = q * (1.0f / 1024.0f) - mean * mean;
    float rstd = rsqrtf(var + LN_EPS);

    float4 g1 = ((const float4*)gat)[t];
    float4 b1 = ((const float4*)bat)[t];
    float u[4];
    u[0] = (h[0] - mean) * rstd * g1.x + b1.x + xv.x;
    u[1] = (h[1] - mean) * rstd * g1.y + b1.y + xv.y;
    u[2] = (h[2] - mean) * rstd * g1.z + b1.z + xv.z;
    u[3] = (h[3] - mean) * rstd * g1.w + b1.w + xv.w;
    __syncthreads();   // reuse smem

    // --- LN 2 ---
    s = u[0] + u[1] + u[2] + u[3];
    q = u[0]*u[0] + u[1]*u[1] + u[2]*u[2] + u[3]*u[3];
    s = warp_sum(s); q = warp_sum(q);
    if (lane == 0) { rs[wid] = s; rq[wid] = q; }
    __syncthreads();
    s = rs[0]; q = rq[0];
    #pragma unroll
    for (int i = 1; i < 8; i++) { s += rs[i]; q += rq[i]; }
    mean = s * (1.0f / 1024.0f);
    var  = q * (1.0f / 1024.0f) - mean * mean;
    rstd = rsqrtf(var + LN_EPS);

    float4 g2 = ((const float4*)gln)[t];
    float4 b2 = ((const float4*)bln)[t];
    float4 o, orr;
    o.x = (u[0] - mean) * rstd * g2.x + b2.x;
    o.y = (u[1] - mean) * rstd * g2.y + b2.y;
    o.z = (u[2] - mean) * rstd * g2.z + b2.z;
    o.w = (u[3] - mean) * rstd * g2.w + b2.w;
    orr.x = to_tf32(o.x); orr.y = to_tf32(o.y);
    orr.z = to_tf32(o.z); orr.w = to_tf32(o.w);
    ((float4*)(H  + row * 1024))[t] = o;
    ((float4*)(Hr + row * 1024))[t] = orr;
}

// ---------------- launcher ---------------------------------------------------
extern "C" void kernel_launch(void* const* d_in, const int* in_sizes, int n_in,
                              void* d_out, int out_size)
{
    const float* x   = (const float*)d_in[0];
    const float* Wq  = (const float*)d_in[1];
    const float* bq  = (const float*)d_in[2];
    const float* Wk  = (const float*)d_in[3];
    const float* bk  = (const float*)d_in[4];
    const float* Wv  = (const float*)d_in[5];
    const float* bv  = (const float*)d_in[6];
    const float* gat = (const float*)d_in[7];
    const float* bat = (const float*)d_in[8];
    const float* gln = (const float*)d_in[9];
    const float* bln = (const float*)d_in[10];
    const float* W1  = (const float*)d_in[11];
    const float* c1  = (const float*)d_in[12];
    const float* W2  = (const float*)d_in[13];
    const float* c2  = (const float*)d_in[14];
    float* out = (float*)d_out;

    float *xr, *WqT, *WkT, *WvT, *W1T, *W2T, *Q, *K, *V, *VT, *P, *O, *H, *Hr, *H1, *H2;
    cudaGetSymbolAddress((void**)&xr,  g_xr);
    cudaGetSymbolAddress((void**)&WqT, g_WqT);
    cudaGetSymbolAddress((void**)&WkT, g_WkT);
    cudaGetSymbolAddress((void**)&WvT, g_WvT);
    cudaGetSymbolAddress((void**)&W1T, g_W1T);
    cudaGetSymbolAddress((void**)&W2T, g_W2T);
    cudaGetSymbolAddress((void**)&Q,   g_Q);
    cudaGetSymbolAddress((void**)&K,   g_K);
    cudaGetSymbolAddress((void**)&V,   g_V);
    cudaGetSymbolAddress((void**)&VT,  g_VT);
    cudaGetSymbolAddress((void**)&P,   g_P);
    cudaGetSymbolAddress((void**)&O,   g_O);
    cudaGetSymbolAddress((void**)&H,   g_H);
    cudaGetSymbolAddress((void**)&Hr,  g_Hr);
    cudaGetSymbolAddress((void**)&H1,  g_H1);
    cudaGetSymbolAddress((void**)&H2,  g_H2);

    cudaFuncSetAttribute(tgemm<0,0>, cudaFuncAttributeMaxDynamicSharedMemorySize, SMEM_BYTES);
    cudaFuncSetAttribute(tgemm<0,1>, cudaFuncAttributeMaxDynamicSharedMemorySize, SMEM_BYTES);
    cudaFuncSetAttribute(tgemm<1,0>, cudaFuncAttributeMaxDynamicSharedMemorySize, SMEM_BYTES);
    cudaFuncSetAttribute(tgemm<1,1>, cudaFuncAttributeMaxDynamicSharedMemorySize, SMEM_BYTES);

    const dim3 blk(256);
    const size_t sSD = (size_t)SS * DD;
    const size_t sSS = (size_t)SS * SS;

    // 1: round x
    round_copy<<<(MTOT * DD / 4 + 255) / 256, blk>>>(x, xr, (size_t)MTOT * DD / 4);
    // 2: all weight transposes in one launch
    transpose5<<<dim3(32, 32, 5), dim3(32, 8)>>>(Wq, Wk, Wv, W1, W2,
                                                 WqT, WkT, WvT, W1T, W2T);

    const dim3 gQKV(DD / 256, MTOT / 128, 1);      // (4, 64)
    const dim3 gSC (SS / 256, SS / 128, BB);       // (8, 16, 4)
    const dim3 gPV (DD / 256, SS / 128, BB);       // (4, 16, 4)

    // 3-5: QKV projections
    tgemm<0,1><<<gQKV, blk, SMEM_BYTES>>>(xr, WqT, bq, Q, DD, DD, DD, DD, 1.0f, 0, 0, 0);
    tgemm<0,1><<<gQKV, blk, SMEM_BYTES>>>(xr, WkT, bk, K, DD, DD, DD, DD, 1.0f, 0, 0, 0);
    tgemm<0,0><<<gQKV, blk, SMEM_BYTES>>>(xr, WvT, bv, V, DD, DD, DD, DD, 1.0f, 0, 0, 0);

    // 6: scores = (Q @ K^T) / 8   <-- this is the launch ncu -s 5 -c 1 profiles
    tgemm<0,0><<<gSC, blk, SMEM_BYTES>>>(Q, K, nullptr, P, DD, DD, SS, DD, INV_SCALE, sSD, sSD, sSS);

    // 7: V^T per batch: [S,D] -> [D,S], rounded
    transpose_round<<<dim3(DD / 32, SS / 32, BB), dim3(32, 8)>>>(V, VT, SS, DD, sSD, sSD);

    // 8: softmax (rounds P to tf32 at store)
    softmax2048<<<BB * SS, blk>>>(P);

    // 9: O = P @ V  (B = V^T stored [D,S])
    tgemm<0,0><<<gPV, blk, SMEM_BYTES>>>(P, VT, nullptr, O, SS, SS, DD, SS, 1.0f, sSS, sSD, sSD);

    // 10: fused double-LN: H = LN(LN(O+x)+x), Hr = tf32(H)
    ln2_fused<<<MTOT, blk>>>(O, x, gat, bat, gln, bln, H, Hr);

    // 11-12: FFN
    tgemm<1,1><<<gQKV, blk, SMEM_BYTES>>>(Hr, W1T, c1, H1, DD, DD, DD, DD, 1.0f, 0, 0, 0);
    tgemm<1,0><<<gQKV, blk, SMEM_BYTES>>>(H1, W2T, c2, H2, DD, DD, DD, DD, 1.0f, 0, 0, 0);

    // 13: out = LN(h2 + h)
    add_ln1024<<<MTOT, blk>>>(H2, H, gln, bln, out);
}

// round 5
// speedup vs baseline: 3.9209x; 1.0962x over previous
#include <cuda_runtime.h>
#include <cstdint>
#include <math.h>
#include <stddef.h>

// Problem constants
#define BB 4
#define SS 2048
#define DD 1024
#define MTOT (BB * SS)          // 8192
#define LN_EPS 1e-5f
#define INV_SCALE 0.125f        // 1/sqrt(64)

// ---------------- scratch (device globals; no allocation allowed) ----------
__device__ float g_xr [MTOT * DD];             // round(x)
__device__ float g_WqT[DD * DD];
__device__ float g_WkT[DD * DD];
__device__ float g_WvT[DD * DD];
__device__ float g_W1T[DD * DD];
__device__ float g_W2T[DD * DD];
__device__ float g_Q  [MTOT * DD];             // rounded
__device__ float g_K  [MTOT * DD];             // rounded
__device__ float g_V  [MTOT * DD];
__device__ float g_VT [MTOT * DD];             // per-batch [D,S], rounded
__device__ float g_P  [(size_t)BB * SS * SS];  // scores / probs (64 MB)
__device__ float g_O  [MTOT * DD];
__device__ float g_H  [MTOT * DD];
__device__ float g_Hr [MTOT * DD];             // rounded copy of H
__device__ float g_H1 [MTOT * DD];             // rounded
__device__ float g_H2 [MTOT * DD];

// ---------------- helpers ---------------------------------------------------
__device__ __forceinline__ uint32_t smem_u32(const void* p) {
    uint32_t a;
    asm("{ .reg .u64 t; cvta.to.shared.u64 t, %1; cvt.u32.u64 %0, t; }" : "=r"(a) : "l"(p));
    return a;
}
__device__ __forceinline__ float to_tf32(float x) {
    float r;
    asm("cvt.rna.tf32.f32 %0, %1;" : "=f"(r) : "f"(x));
    return r;
}
__device__ __forceinline__ void cpa16(uint32_t dst, const void* src) {
    asm volatile("cp.async.cg.shared.global [%0], [%1], 16;" :: "r"(dst), "l"(src));
}
#define CP_COMMIT() asm volatile("cp.async.commit_group;" ::: "memory")
#define CP_WAIT2()  asm volatile("cp.async.wait_group 2;" ::: "memory")

__device__ __forceinline__ float gelu_exact(float x) {
    return 0.5f * x * (1.0f + erff(x * 0.70710678118654752f));
}
__device__ __forceinline__ float warp_max(float v) {
    #pragma unroll
    for (int o = 16; o > 0; o >>= 1) v = fmaxf(v, __shfl_xor_sync(0xffffffffu, v, o));
    return v;
}
__device__ __forceinline__ float warp_sum(float v) {
    #pragma unroll
    for (int o = 16; o > 0; o >>= 1) v += __shfl_xor_sync(0xffffffffu, v, o);
    return v;
}

// mma.sync m16n8k8 tf32 (baseline PTX)
__device__ __forceinline__ void mma_tf32(float* d, const uint32_t* a, const uint32_t* b) {
    asm volatile(
        "mma.sync.aligned.m16n8k8.row.col.f32.tf32.tf32.f32 "
        "{%0,%1,%2,%3}, {%4,%5,%6,%7}, {%8,%9}, {%0,%1,%2,%3};"
        : "+f"(d[0]), "+f"(d[1]), "+f"(d[2]), "+f"(d[3])
        : "r"(a[0]), "r"(a[1]), "r"(a[2]), "r"(a[3]), "r"(b[0]), "r"(b[1]));
}
// ldmatrix x4 (b16 granularity; 32-bit elements as 8x4 f32 tiles)
__device__ __forceinline__ void ldsm4(uint32_t* r, uint32_t addr) {
    asm volatile("ldmatrix.sync.aligned.m8n8.x4.shared.b16 {%0,%1,%2,%3}, [%4];"
        : "=r"(r[0]), "=r"(r[1]), "=r"(r[2]), "=r"(r[3]) : "r"(addr));
}

// ---------------- tf32 tensor GEMM ------------------------------------------
// C[M,N] = A[M,K] @ B^T, B stored [N,K] row-major (both K-major).
// CTA tile 128x256, 512 threads (16 warps), warp tile 64x32, BK=32,
// 3-stage cp.async ring.
static constexpr int STAGE_BYTES = (128 + 256) * 32 * 4;        // 49152
static constexpr int SMEM_BYTES  = 3 * STAGE_BYTES;             // 147456

// swizzled byte offset within a tile of 128B rows
#define SWA(row, colf) ((row) * 128 + ((((colf) * 4) ^ (((row) & 7) << 4))))

template<int DOGELU, int ROUND>
__global__ __launch_bounds__(512, 1)
void tgemm(const float* __restrict__ A, const float* __restrict__ B,
           const float* __restrict__ bias, float* __restrict__ C,
           int ldA, int ldB, int ldC, int K, float scale,
           size_t strA, size_t strB, size_t strC)
{
    extern __shared__ __align__(1024) char smem[];
    const uint32_t sb = smem_u32(smem);
    const int tid  = threadIdx.x;
    const int lane = tid & 31;
    const int wid  = tid >> 5;
    const int warpRow = (wid & 1) * 64;    // 2 m-groups of 64
    const int warpCol = (wid >> 1) * 32;   // 8 n-groups of 32

    const int m0 = blockIdx.y * 128;
    const int n0 = blockIdx.x * 256;
    A += (size_t)blockIdx.z * strA + (size_t)m0 * ldA;
    B += (size_t)blockIdx.z * strB + (size_t)n0 * ldB;
    C += (size_t)blockIdx.z * strC;

    float acc[4][4][4];
    #pragma unroll
    for (int i = 0; i < 4; i++)
        #pragma unroll
        for (int j = 0; j < 4; j++)
            #pragma unroll
            for (int q = 0; q < 4; q++) acc[i][j][q] = 0.0f;

    const int NK = K >> 5;

    // loader indices (row = idx>>3, 16B segment = idx&7); 512 threads
    const int arow0 = tid >> 3;       // 0..63
    const int aks   = (tid & 7);

    auto load_stage = [&](int kt, int st) {
        const int koff = kt * 32;
        const uint32_t stb = sb + st * STAGE_BYTES;
        #pragma unroll
        for (int i = 0; i < 2; i++) {
            const int row = arow0 + i * 64;
            cpa16(stb + SWA(row, aks * 4),
                  A + (size_t)row * ldA + koff + aks * 4);
        }
        const uint32_t stbB = stb + 16384;
        #pragma unroll
        for (int i = 0; i < 4; i++) {
            const int row = arow0 + i * 64;
            cpa16(stbB + SWA(row, aks * 4),
                  B + (size_t)row * ldB + koff + aks * 4);
        }
        CP_COMMIT();
    };

    load_stage(0, 0);
    if (NK > 1) load_stage(1, 1);
    if (NK > 2) load_stage(2, 2);

    // ---- precomputed per-lane ldmatrix base offsets (stage-relative) ----
    const int sub = lane >> 3;
    const int l7  = lane & 7;
    uint32_t aoff[4], boff[2];
    {
        // A submatrix order: m0=(r0-7,c0-3) m1=(r8-15,c0-3) m2=(r0-7,c4-7) m3=(r8-15,c4-7)
        const int arow = l7 + (sub & 1) * 8;
        const int acol = (sub >> 1) * 4;
        #pragma unroll
        for (int ma = 0; ma < 4; ma++) {
            const int r = warpRow + ma * 16 + arow;
            aoff[ma] = SWA(r, acol);
        }
        // B: m0=(n0-7,k0-3) m1=(n0-7,k4-7) m2=(n8-15,k0-3) m3=(n8-15,k4-7)
        const int brow = l7 + (sub >> 1) * 8;
        const int bcol = (sub & 1) * 4;
        #pragma unroll
        for (int p = 0; p < 2; p++) {
            const int r = warpCol + p * 16 + brow;
            boff[p] = SWA(r, bcol);
        }
    }

    for (int kt = 0; kt < NK; kt++) {
        CP_WAIT2();
        __syncthreads();

        const uint32_t stbA = sb + (kt % 3) * STAGE_BYTES;
        const uint32_t stbB = stbA + 16384;

        #pragma unroll
        for (int kk = 0; kk < 4; kk++) {
            const uint32_t kx = kk * 32;   // byte XOR for this k-step

            uint32_t af[4][4];
            #pragma unroll
            for (int ma = 0; ma < 4; ma++)
                ldsm4(af[ma], stbA + (aoff[ma] ^ kx));
            uint32_t bf[2][4];
            #pragma unroll
            for (int p = 0; p < 2; p++)
                ldsm4(bf[p], stbB + (boff[p] ^ kx));

            #pragma unroll
            for (int ma = 0; ma < 4; ma++)
                #pragma unroll
                for (int nb = 0; nb < 4; nb++)
                    mma_tf32(acc[ma][nb], af[ma], &bf[nb >> 1][(nb & 1) * 2]);
        }
        __syncthreads();

        if (kt + 3 < NK) load_stage(kt + 3, kt % 3);
    }

    // ---- epilogue ----
    const int r_lo = lane >> 2;
    const int c_lo = lane & 3;
    #pragma unroll
    for (int ma = 0; ma < 4; ma++) {
        const int r0 = m0 + warpRow + ma * 16 + r_lo;
        const int r1 = r0 + 8;
        #pragma unroll
        for (int nb = 0; nb < 4; nb++) {
            const int col = n0 + warpCol + nb * 8 + c_lo * 2;
            float b0 = 0.0f, b1 = 0.0f;
            if (bias) {
                float2 bv = *(const float2*)&bias[col];
                b0 = bv.x; b1 = bv.y;
            }
            float v0 = acc[ma][nb][0] * scale + b0;
            float v1 = acc[ma][nb][1] * scale + b1;
            float v2 = acc[ma][nb][2] * scale + b0;
            float v3 = acc[ma][nb][3] * scale + b1;
            if (DOGELU) {
                v0 = gelu_exact(v0); v1 = gelu_exact(v1);
                v2 = gelu_exact(v2); v3 = gelu_exact(v3);
            }
            if (ROUND) {
                v0 = to_tf32(v0); v1 = to_tf32(v1);
                v2 = to_tf32(v2); v3 = to_tf32(v3);
            }
            *(float2*)&C[(size_t)r0 * ldC + col] = make_float2(v0, v1);
            *(float2*)&C[(size_t)r1 * ldC + col] = make_float2(v2, v3);
        }
    }
}

// ---------------- elementwise / reduction kernels ---------------------------
__global__ __launch_bounds__(256)
void round_copy(const float* __restrict__ in, float* __restrict__ out, size_t n4)
{
    size_t i = (size_t)blockIdx.x * blockDim.x + threadIdx.x;
    if (i < n4) {
        float4 v = ((const float4*)in)[i];
        v.x = to_tf32(v.x); v.y = to_tf32(v.y);
        v.z = to_tf32(v.z); v.w = to_tf32(v.w);
        ((float4*)out)[i] = v;
    }
}

// transpose+round for the five 1024x1024 weights in one launch (z selects)
__global__ __launch_bounds__(256)
void transpose5(const float* __restrict__ s0, const float* __restrict__ s1,
                const float* __restrict__ s2, const float* __restrict__ s3,
                const float* __restrict__ s4,
                float* __restrict__ d0, float* __restrict__ d1,
                float* __restrict__ d2, float* __restrict__ d3,
                float* __restrict__ d4)
{
    __shared__ float tile[32][33];
    const int z = blockIdx.z;
    const float* in = (z == 0) ? s0 : (z == 1) ? s1 : (z == 2) ? s2 : (z == 3) ? s3 : s4;
    float* out      = (z == 0) ? d0 : (z == 1) ? d1 : (z == 2) ? d2 : (z == 3) ? d3 : d4;
    const int c0 = blockIdx.x * 32, r0 = blockIdx.y * 32;
    #pragma unroll
    for (int i = 0; i < 4; i++)
        tile[threadIdx.y + i * 8][threadIdx.x] =
            in[(size_t)(r0 + threadIdx.y + i * 8) * DD + c0 + threadIdx.x];
    __syncthreads();
    #pragma unroll
    for (int i = 0; i < 4; i++)
        out[(size_t)(c0 + threadIdx.y + i * 8) * DD + r0 + threadIdx.x] =
            to_tf32(tile[threadIdx.x][threadIdx.y + i * 8]);
}

// out[c, r] = round(in[r, c]); per-batch, block (32, 8)
__global__ __launch_bounds__(256)
void transpose_round(const float* __restrict__ in, float* __restrict__ out,
                     int rows, int cols, size_t sIn, size_t sOut)
{
    __shared__ float tile[32][33];
    in  += (size_t)blockIdx.z * sIn;
    out += (size_t)blockIdx.z * sOut;
    const int c0 = blockIdx.x * 32, r0 = blockIdx.y * 32;
    #pragma unroll
    for (int i = 0; i < 4; i++)
        tile[threadIdx.y + i * 8][threadIdx.x] =
            in[(size_t)(r0 + threadIdx.y + i * 8) * cols + c0 + threadIdx.x];
    __syncthreads();
    #pragma unroll
    for (int i = 0; i < 4; i++)
        out[(size_t)(c0 + threadIdx.y + i * 8) * rows + r0 + threadIdx.x] =
            to_tf32(tile[threadIdx.x][threadIdx.y + i * 8]);
}

__global__ __launch_bounds__(256)
void softmax2048(float* __restrict__ P)
{
    float* p = P + (size_t)blockIdx.x * 2048;
    const int t = threadIdx.x, lane = t & 31, wid = t >> 5;
    __shared__ float red[8];

    float4 v0 = ((const float4*)p)[t];
    float4 v1 = ((const float4*)p)[256 + t];

    float mx = fmaxf(fmaxf(fmaxf(v0.x, v0.y), fmaxf(v0.z, v0.w)),
                     fmaxf(fmaxf(v1.x, v1.y), fmaxf(v1.z, v1.w)));
    mx = warp_max(mx);
    if (lane == 0) red[wid] = mx;
    __syncthreads();
    mx = red[0];
    #pragma unroll
    for (int i = 1; i < 8; i++) mx = fmaxf(mx, red[i]);
    __syncthreads();

    v0.x = expf(v0.x - mx); v0.y = expf(v0.y - mx);
    v0.z = expf(v0.z - mx); v0.w = expf(v0.w - mx);
    v1.x = expf(v1.x - mx); v1.y = expf(v1.y - mx);
    v1.z = expf(v1.z - mx); v1.w = expf(v1.w - mx);

    float s = (v0.x + v0.y + v0.z + v0.w) + (v1.x + v1.y + v1.z + v1.w);
    s = warp_sum(s);
    if (lane == 0) red[wid] = s;
    __syncthreads();
    s = red[0];
    #pragma unroll
    for (int i = 1; i < 8; i++) s += red[i];

    const float inv = 1.0f / s;
    v0.x = to_tf32(v0.x * inv); v0.y = to_tf32(v0.y * inv);
    v0.z = to_tf32(v0.z * inv); v0.w = to_tf32(v0.w * inv);
    v1.x = to_tf32(v1.x * inv); v1.y = to_tf32(v1.y * inv);
    v1.z = to_tf32(v1.z * inv); v1.w = to_tf32(v1.w * inv);
    ((float4*)p)[t]       = v0;
    ((float4*)p)[256 + t] = v1;
}

// single add+LN (used for final output)
__global__ __launch_bounds__(256)
void add_ln1024(const float* __restrict__ A, const float* __restrict__ R,
                const float* __restrict__ gamma, const float* __restrict__ beta,
                float* __restrict__ out)
{
    const size_t row = blockIdx.x;
    const int t = threadIdx.x, lane = t & 31, wid = t >> 5;
    __shared__ float rs[8], rq[8];

    float4 a = ((const float4*)(A + row * 1024))[t];
    float4 r = ((const float4*)(R + row * 1024))[t];
    float h0 = a.x + r.x, h1 = a.y + r.y, h2 = a.z + r.z, h3 = a.w + r.w;

    float s = h0 + h1 + h2 + h3;
    float q = h0 * h0 + h1 * h1 + h2 * h2 + h3 * h3;
    s = warp_sum(s); q = warp_sum(q);
    if (lane == 0) { rs[wid] = s; rq[wid] = q; }
    __syncthreads();
    s = rs[0]; q = rq[0];
    #pragma unroll
    for (int i = 1; i < 8; i++) { s += rs[i]; q += rq[i]; }

    const float mean = s * (1.0f / 1024.0f);
    const float var  = q * (1.0f / 1024.0f) - mean * mean;
    const float rstd = rsqrtf(var + LN_EPS);

    float4 gg = ((const float4*)gamma)[t];
    float4 bb = ((const float4*)beta)[t];
    float4 o;
    o.x = (h0 - mean) * rstd * gg.x + bb.x;
    o.y = (h1 - mean) * rstd * gg.y + bb.y;
    o.z = (h2 - mean) * rstd * gg.z + bb.z;
    o.w = (h3 - mean) * rstd * gg.w + bb.w;
    ((float4*)(out + row * 1024))[t] = o;
}

// fused: at = LN(O + x)*g_at+b_at;  H = LN(at + x)*g_ln+b_ln;  Hr = tf32(H)
__global__ __launch_bounds__(256)
void ln2_fused(const float* __restrict__ O, const float* __restrict__ X,
               const float* __restrict__ gat, const float* __restrict__ bat,
               const float* __restrict__ gln, const float* __restrict__ bln,
               float* __restrict__ H, float* __restrict__ Hr)
{
    const size_t row = blockIdx.x;
    const int t = threadIdx.x, lane = t & 31, wid = t >> 5;
    __shared__ float rs[8], rq[8];

    float4 a = ((const float4*)(O + row * 1024))[t];
    float4 xv = ((const float4*)(X + row * 1024))[t];
    float h[4] = {a.x + xv.x, a.y + xv.y, a.z + xv.z, a.w + xv.w};

    // --- LN 1 ---
    float s = h[0] + h[1] + h[2] + h[3];
    float q = h[0]*h[0] + h[1]*h[1] + h[2]*h[2] + h[3]*h[3];
    s = warp_sum(s); q = warp_sum(q);
    if (lane == 0) { rs[wid] = s; rq[wid] = q; }
    __syncthreads();
    s = rs[0]; q = rq[0];
    #pragma unroll
    for (int i = 1; i < 8; i++) { s += rs[i]; q += rq[i]; }
    float mean = s * (1.0f / 1024.0f);
    float var  = q * (1.0f / 1024.0f) - mean * mean;
    float rstd = rsqrtf(var + LN_EPS);

    float4 g1 = ((const float4*)gat)[t];
    float4 b1 = ((const float4*)bat)[t];
    float u[4];
    u[0] = (h[0] - mean) * rstd * g1.x + b1.x + xv.x;
    u[1] = (h[1] - mean) * rstd * g1.y + b1.y + xv.y;
    u[2] = (h[2] - mean) * rstd * g1.z + b1.z + xv.z;
    u[3] = (h[3] - mean) * rstd * g1.w + b1.w + xv.w;
    __syncthreads();   // reuse smem

    // --- LN 2 ---
    s = u[0] + u[1] + u[2] + u[3];
    q = u[0]*u[0] + u[1]*u[1] + u[2]*u[2] + u[3]*u[3];
    s = warp_sum(s); q = warp_sum(q);
    if (lane == 0) { rs[wid] = s; rq[wid] = q; }
    __syncthreads();
    s = rs[0]; q = rq[0];
    #pragma unroll
    for (int i = 1; i < 8; i++) { s += rs[i]; q += rq[i]; }
    mean = s * (1.0f / 1024.0f);
    var  = q * (1.0f / 1024.0f) - mean * mean;
    rstd = rsqrtf(var + LN_EPS);

    float4 g2 = ((const float4*)gln)[t];
    float4 b2 = ((const float4*)bln)[t];
    float4 o, orr;
    o.x = (u[0] - mean) * rstd * g2.x + b2.x;
    o.y = (u[1] - mean) * rstd * g2.y + b2.y;
    o.z = (u[2] - mean) * rstd * g2.z + b2.z;
    o.w = (u[3] - mean) * rstd * g2.w + b2.w;
    orr.x = to_tf32(o.x); orr.y = to_tf32(o.y);
    orr.z = to_tf32(o.z); orr.w = to_tf32(o.w);
    ((float4*)(H  + row * 1024))[t] = o;
    ((float4*)(Hr + row * 1024))[t] = orr;
}

// ---------------- launcher ---------------------------------------------------
extern "C" void kernel_launch(void* const* d_in, const int* in_sizes, int n_in,
                              void* d_out, int out_size)
{
    const float* x   = (const float*)d_in[0];
    const float* Wq  = (const float*)d_in[1];
    const float* bq  = (const float*)d_in[2];
    const float* Wk  = (const float*)d_in[3];
    const float* bk  = (const float*)d_in[4];
    const float* Wv  = (const float*)d_in[5];
    const float* bv  = (const float*)d_in[6];
    const float* gat = (const float*)d_in[7];
    const float* bat = (const float*)d_in[8];
    const float* gln = (const float*)d_in[9];
    const float* bln = (const float*)d_in[10];
    const float* W1  = (const float*)d_in[11];
    const float* c1  = (const float*)d_in[12];
    const float* W2  = (const float*)d_in[13];
    const float* c2  = (const float*)d_in[14];
    float* out = (float*)d_out;

    float *xr, *WqT, *WkT, *WvT, *W1T, *W2T, *Q, *K, *V, *VT, *P, *O, *H, *Hr, *H1, *H2;
    cudaGetSymbolAddress((void**)&xr,  g_xr);
    cudaGetSymbolAddress((void**)&WqT, g_WqT);
    cudaGetSymbolAddress((void**)&WkT, g_WkT);
    cudaGetSymbolAddress((void**)&WvT, g_WvT);
    cudaGetSymbolAddress((void**)&W1T, g_W1T);
    cudaGetSymbolAddress((void**)&W2T, g_W2T);
    cudaGetSymbolAddress((void**)&Q,   g_Q);
    cudaGetSymbolAddress((void**)&K,   g_K);
    cudaGetSymbolAddress((void**)&V,   g_V);
    cudaGetSymbolAddress((void**)&VT,  g_VT);
    cudaGetSymbolAddress((void**)&P,   g_P);
    cudaGetSymbolAddress((void**)&O,   g_O);
    cudaGetSymbolAddress((void**)&H,   g_H);
    cudaGetSymbolAddress((void**)&Hr,  g_Hr);
    cudaGetSymbolAddress((void**)&H1,  g_H1);
    cudaGetSymbolAddress((void**)&H2,  g_H2);

    cudaFuncSetAttribute(tgemm<0,0>, cudaFuncAttributeMaxDynamicSharedMemorySize, SMEM_BYTES);
    cudaFuncSetAttribute(tgemm<0,1>, cudaFuncAttributeMaxDynamicSharedMemorySize, SMEM_BYTES);
    cudaFuncSetAttribute(tgemm<1,0>, cudaFuncAttributeMaxDynamicSharedMemorySize, SMEM_BYTES);
    cudaFuncSetAttribute(tgemm<1,1>, cudaFuncAttributeMaxDynamicSharedMemorySize, SMEM_BYTES);

    const dim3 blk(256);
    const dim3 gblk(512);
    const size_t sSD = (size_t)SS * DD;
    const size_t sSS = (size_t)SS * SS;

    // 1: round x
    round_copy<<<(MTOT * DD / 4 + 255) / 256, blk>>>(x, xr, (size_t)MTOT * DD / 4);
    // 2: all weight transposes in one launch
    transpose5<<<dim3(32, 32, 5), dim3(32, 8)>>>(Wq, Wk, Wv, W1, W2,
                                                 WqT, WkT, WvT, W1T, W2T);

    const dim3 gQKV(DD / 256, MTOT / 128, 1);      // (4, 64)
    const dim3 gSC (SS / 256, SS / 128, BB);       // (8, 16, 4)
    const dim3 gPV (DD / 256, SS / 128, BB);       // (4, 16, 4)

    // 3-5: QKV projections
    tgemm<0,1><<<gQKV, gblk, SMEM_BYTES>>>(xr, WqT, bq, Q, DD, DD, DD, DD, 1.0f, 0, 0, 0);
    tgemm<0,1><<<gQKV, gblk, SMEM_BYTES>>>(xr, WkT, bk, K, DD, DD, DD, DD, 1.0f, 0, 0, 0);
    tgemm<0,0><<<gQKV, gblk, SMEM_BYTES>>>(xr, WvT, bv, V, DD, DD, DD, DD, 1.0f, 0, 0, 0);

    // 6: scores = (Q @ K^T) / 8
    tgemm<0,0><<<gSC, gblk, SMEM_BYTES>>>(Q, K, nullptr, P, DD, DD, SS, DD, INV_SCALE, sSD, sSD, sSS);

    // 7: V^T per batch: [S,D] -> [D,S], rounded
    transpose_round<<<dim3(DD / 32, SS / 32, BB), dim3(32, 8)>>>(V, VT, SS, DD, sSD, sSD);

    // 8: softmax (rounds P to tf32 at store)
    softmax2048<<<BB * SS, blk>>>(P);

    // 9: O = P @ V  (B = V^T stored [D,S])
    tgemm<0,0><<<gPV, gblk, SMEM_BYTES>>>(P, VT, nullptr, O, SS, SS, DD, SS, 1.0f, sSS, sSD, sSD);

    // 10: fused double-LN: H = LN(LN(O+x)+x), Hr = tf32(H)
    ln2_fused<<<MTOT, blk>>>(O, x, gat, bat, gln, bln, H, Hr);

    // 11-12: FFN
    tgemm<1,1><<<gQKV, gblk, SMEM_BYTES>>>(Hr, W1T, c1, H1, DD, DD, DD, DD, 1.0f, 0, 0, 0);
    tgemm<1,0><<<gQKV, gblk, SMEM_BYTES>>>(H1, W2T, c2, H2, DD, DD, DD, DD, 1.0f, 0, 0, 0);

    // 13: out = LN(h2 + h)
    add_ln1024<<<MTOT, blk>>>(H2, H, gln, bln, out);
}

// round 6
// speedup vs baseline: 4.2162x; 1.0753x over previous
#include <cuda_runtime.h>
#include <cstdint>
#include <math.h>
#include <stddef.h>

// Problem constants
#define BB 4
#define SS 2048
#define DD 1024
#define MTOT (BB * SS)          // 8192
#define LN_EPS 1e-5f
#define INV_SCALE 0.125f        // 1/sqrt(64)

// ---------------- scratch (device globals; no allocation allowed) ----------
__device__ float g_xr [MTOT * DD];             // round(x)
__device__ float g_WqT[DD * DD];
__device__ float g_WkT[DD * DD];
__device__ float g_WvT[DD * DD];
__device__ float g_W1T[DD * DD];
__device__ float g_W2T[DD * DD];
__device__ float g_Q  [MTOT * DD];             // rounded
__device__ float g_K  [MTOT * DD];             // rounded
__device__ float g_V  [MTOT * DD];
__device__ float g_VT [MTOT * DD];             // per-batch [D,S], rounded
__device__ float g_P  [(size_t)BB * SS * SS];  // scores / probs (64 MB)
__device__ float g_O  [MTOT * DD];
__device__ float g_H  [MTOT * DD];
__device__ float g_Hr [MTOT * DD];             // rounded copy of H
__device__ float g_H1 [MTOT * DD];             // rounded
__device__ float g_H2 [MTOT * DD];

// ---------------- helpers ---------------------------------------------------
__device__ __forceinline__ uint32_t smem_u32(const void* p) {
    uint32_t a;
    asm("{ .reg .u64 t; cvta.to.shared.u64 t, %1; cvt.u32.u64 %0, t; }" : "=r"(a) : "l"(p));
    return a;
}
__device__ __forceinline__ float to_tf32(float x) {
    float r;
    asm("cvt.rna.tf32.f32 %0, %1;" : "=f"(r) : "f"(x));
    return r;
}
__device__ __forceinline__ void cpa16(uint32_t dst, const void* src) {
    asm volatile("cp.async.cg.shared.global [%0], [%1], 16;" :: "r"(dst), "l"(src));
}
#define CP_COMMIT() asm volatile("cp.async.commit_group;" ::: "memory")
#define CP_WAIT2()  asm volatile("cp.async.wait_group 2;" ::: "memory")

__device__ __forceinline__ float gelu_exact(float x) {
    return 0.5f * x * (1.0f + erff(x * 0.70710678118654752f));
}
__device__ __forceinline__ float warp_max(float v) {
    #pragma unroll
    for (int o = 16; o > 0; o >>= 1) v = fmaxf(v, __shfl_xor_sync(0xffffffffu, v, o));
    return v;
}
__device__ __forceinline__ float warp_sum(float v) {
    #pragma unroll
    for (int o = 16; o > 0; o >>= 1) v += __shfl_xor_sync(0xffffffffu, v, o);
    return v;
}

// mma.sync m16n8k8 tf32 (baseline PTX)
__device__ __forceinline__ void mma_tf32(float* d, const uint32_t* a, const uint32_t* b) {
    asm volatile(
        "mma.sync.aligned.m16n8k8.row.col.f32.tf32.tf32.f32 "
        "{%0,%1,%2,%3}, {%4,%5,%6,%7}, {%8,%9}, {%0,%1,%2,%3};"
        : "+f"(d[0]), "+f"(d[1]), "+f"(d[2]), "+f"(d[3])
        : "r"(a[0]), "r"(a[1]), "r"(a[2]), "r"(a[3]), "r"(b[0]), "r"(b[1]));
}
// ldmatrix x4 (b16 granularity; 32-bit elements as 8x4 f32 tiles)
__device__ __forceinline__ void ldsm4(uint32_t* r, uint32_t addr) {
    asm volatile("ldmatrix.sync.aligned.m8n8.x4.shared.b16 {%0,%1,%2,%3}, [%4];"
        : "=r"(r[0]), "=r"(r[1]), "=r"(r[2]), "=r"(r[3]) : "r"(addr));
}

// ---------------- tf32 tensor GEMM ------------------------------------------
// C[M,N] = A[M,K] @ B^T, B stored [N,K] row-major (both K-major).
// CTA tile 128x128, 256 threads (8 warps), warp tile 64x32, BK=32,
// 3-stage cp.async ring, 2 CTAs/SM.
static constexpr int STAGE_BYTES = (128 + 128) * 32 * 4;        // 32768
static constexpr int SMEM_BYTES  = 3 * STAGE_BYTES;             // 98304

// swizzled byte offset within a tile of 128B rows
#define SWA(row, colf) ((row) * 128 + ((((colf) * 4) ^ (((row) & 7) << 4))))

template<int DOGELU, int ROUND>
__global__ __launch_bounds__(256, 2)
void tgemm(const float* __restrict__ A, const float* __restrict__ B,
           const float* __restrict__ bias, float* __restrict__ C,
           int ldA, int ldB, int ldC, int K, float scale,
           size_t strA, size_t strB, size_t strC)
{
    extern __shared__ __align__(1024) char smem[];
    const uint32_t sb = smem_u32(smem);
    const int tid  = threadIdx.x;
    const int lane = tid & 31;
    const int wid  = tid >> 5;
    const int warpRow = (wid & 1) * 64;    // 2 m-groups of 64
    const int warpCol = (wid >> 1) * 32;   // 4 n-groups of 32

    const int m0 = blockIdx.y * 128;
    const int n0 = blockIdx.x * 128;
    A += (size_t)blockIdx.z * strA + (size_t)m0 * ldA;
    B += (size_t)blockIdx.z * strB + (size_t)n0 * ldB;
    C += (size_t)blockIdx.z * strC;

    float acc[4][4][4];
    #pragma unroll
    for (int i = 0; i < 4; i++)
        #pragma unroll
        for (int j = 0; j < 4; j++)
            #pragma unroll
            for (int q = 0; q < 4; q++) acc[i][j][q] = 0.0f;

    const int NK = K >> 5;

    // loader indices (row = idx>>3, 16B segment = idx&7); 256 threads
    const int arow0 = tid >> 3;       // 0..31
    const int aks   = (tid & 7);

    auto load_stage = [&](int kt, int st) {
        const int koff = kt * 32;
        const uint32_t stb = sb + st * STAGE_BYTES;
        #pragma unroll
        for (int i = 0; i < 4; i++) {
            const int row = arow0 + i * 32;
            cpa16(stb + SWA(row, aks * 4),
                  A + (size_t)row * ldA + koff + aks * 4);
        }
        const uint32_t stbB = stb + 16384;
        #pragma unroll
        for (int i = 0; i < 4; i++) {
            const int row = arow0 + i * 32;
            cpa16(stbB + SWA(row, aks * 4),
                  B + (size_t)row * ldB + koff + aks * 4);
        }
        CP_COMMIT();
    };

    load_stage(0, 0);
    if (NK > 1) load_stage(1, 1);
    if (NK > 2) load_stage(2, 2);

    // ---- precomputed per-lane ldmatrix base offsets (stage-relative) ----
    const int sub = lane >> 3;
    const int l7  = lane & 7;
    uint32_t aoff[4], boff[2];
    {
        // A submatrix order: m0=(r0-7,c0-3) m1=(r8-15,c0-3) m2=(r0-7,c4-7) m3=(r8-15,c4-7)
        const int arow = l7 + (sub & 1) * 8;
        const int acol = (sub >> 1) * 4;
        #pragma unroll
        for (int ma = 0; ma < 4; ma++) {
            const int r = warpRow + ma * 16 + arow;
            aoff[ma] = SWA(r, acol);
        }
        // B: m0=(n0-7,k0-3) m1=(n0-7,k4-7) m2=(n8-15,k0-3) m3=(n8-15,k4-7)
        const int brow = l7 + (sub >> 1) * 8;
        const int bcol = (sub & 1) * 4;
        #pragma unroll
        for (int p = 0; p < 2; p++) {
            const int r = warpCol + p * 16 + brow;
            boff[p] = SWA(r, bcol);
        }
    }

    for (int kt = 0; kt < NK; kt++) {
        CP_WAIT2();
        __syncthreads();

        const uint32_t stbA = sb + (kt % 3) * STAGE_BYTES;
        const uint32_t stbB = stbA + 16384;

        #pragma unroll
        for (int kk = 0; kk < 4; kk++) {
            const uint32_t kx = kk * 32;   // byte XOR for this k-step

            uint32_t af[4][4];
            #pragma unroll
            for (int ma = 0; ma < 4; ma++)
                ldsm4(af[ma], stbA + (aoff[ma] ^ kx));
            uint32_t bf[2][4];
            #pragma unroll
            for (int p = 0; p < 2; p++)
                ldsm4(bf[p], stbB + (boff[p] ^ kx));

            #pragma unroll
            for (int ma = 0; ma < 4; ma++)
                #pragma unroll
                for (int nb = 0; nb < 4; nb++)
                    mma_tf32(acc[ma][nb], af[ma], &bf[nb >> 1][(nb & 1) * 2]);
        }
        __syncthreads();

        if (kt + 3 < NK) load_stage(kt + 3, kt % 3);
    }

    // ---- epilogue ----
    const int r_lo = lane >> 2;
    const int c_lo = lane & 3;
    #pragma unroll
    for (int ma = 0; ma < 4; ma++) {
        const int r0 = m0 + warpRow + ma * 16 + r_lo;
        const int r1 = r0 + 8;
        #pragma unroll
        for (int nb = 0; nb < 4; nb++) {
            const int col = n0 + warpCol + nb * 8 + c_lo * 2;
            float b0 = 0.0f, b1 = 0.0f;
            if (bias) {
                float2 bv = *(const float2*)&bias[col];
                b0 = bv.x; b1 = bv.y;
            }
            float v0 = acc[ma][nb][0] * scale + b0;
            float v1 = acc[ma][nb][1] * scale + b1;
            float v2 = acc[ma][nb][2] * scale + b0;
            float v3 = acc[ma][nb][3] * scale + b1;
            if (DOGELU) {
                v0 = gelu_exact(v0); v1 = gelu_exact(v1);
                v2 = gelu_exact(v2); v3 = gelu_exact(v3);
            }
            if (ROUND) {
                v0 = to_tf32(v0); v1 = to_tf32(v1);
                v2 = to_tf32(v2); v3 = to_tf32(v3);
            }
            *(float2*)&C[(size_t)r0 * ldC + col] = make_float2(v0, v1);
            *(float2*)&C[(size_t)r1 * ldC + col] = make_float2(v2, v3);
        }
    }
}

// ---------------- elementwise / reduction kernels ---------------------------
__global__ __launch_bounds__(256)
void round_copy(const float* __restrict__ in, float* __restrict__ out, size_t n4)
{
    size_t i = (size_t)blockIdx.x * blockDim.x + threadIdx.x;
    if (i < n4) {
        float4 v = ((const float4*)in)[i];
        v.x = to_tf32(v.x); v.y = to_tf32(v.y);
        v.z = to_tf32(v.z); v.w = to_tf32(v.w);
        ((float4*)out)[i] = v;
    }
}

// transpose+round for the five 1024x1024 weights in one launch (z selects)
__global__ __launch_bounds__(256)
void transpose5(const float* __restrict__ s0, const float* __restrict__ s1,
                const float* __restrict__ s2, const float* __restrict__ s3,
                const float* __restrict__ s4,
                float* __restrict__ d0, float* __restrict__ d1,
                float* __restrict__ d2, float* __restrict__ d3,
                float* __restrict__ d4)
{
    __shared__ float tile[32][33];
    const int z = blockIdx.z;
    const float* in = (z == 0) ? s0 : (z == 1) ? s1 : (z == 2) ? s2 : (z == 3) ? s3 : s4;
    float* out      = (z == 0) ? d0 : (z == 1) ? d1 : (z == 2) ? d2 : (z == 3) ? d3 : d4;
    const int c0 = blockIdx.x * 32, r0 = blockIdx.y * 32;
    #pragma unroll
    for (int i = 0; i < 4; i++)
        tile[threadIdx.y + i * 8][threadIdx.x] =
            in[(size_t)(r0 + threadIdx.y + i * 8) * DD + c0 + threadIdx.x];
    __syncthreads();
    #pragma unroll
    for (int i = 0; i < 4; i++)
        out[(size_t)(c0 + threadIdx.y + i * 8) * DD + r0 + threadIdx.x] =
            to_tf32(tile[threadIdx.x][threadIdx.y + i * 8]);
}

// out[c, r] = round(in[r, c]); per-batch, block (32, 8)
__global__ __launch_bounds__(256)
void transpose_round(const float* __restrict__ in, float* __restrict__ out,
                     int rows, int cols, size_t sIn, size_t sOut)
{
    __shared__ float tile[32][33];
    in  += (size_t)blockIdx.z * sIn;
    out += (size_t)blockIdx.z * sOut;
    const int c0 = blockIdx.x * 32, r0 = blockIdx.y * 32;
    #pragma unroll
    for (int i = 0; i < 4; i++)
        tile[threadIdx.y + i * 8][threadIdx.x] =
            in[(size_t)(r0 + threadIdx.y + i * 8) * cols + c0 + threadIdx.x];
    __syncthreads();
    #pragma unroll
    for (int i = 0; i < 4; i++)
        out[(size_t)(c0 + threadIdx.y + i * 8) * rows + r0 + threadIdx.x] =
            to_tf32(tile[threadIdx.x][threadIdx.y + i * 8]);
}

__global__ __launch_bounds__(256)
void softmax2048(float* __restrict__ P)
{
    float* p = P + (size_t)blockIdx.x * 2048;
    const int t = threadIdx.x, lane = t & 31, wid = t >> 5;
    __shared__ float red[8];

    float4 v0 = ((const float4*)p)[t];
    float4 v1 = ((const float4*)p)[256 + t];

    float mx = fmaxf(fmaxf(fmaxf(v0.x, v0.y), fmaxf(v0.z, v0.w)),
                     fmaxf(fmaxf(v1.x, v1.y), fmaxf(v1.z, v1.w)));
    mx = warp_max(mx);
    if (lane == 0) red[wid] = mx;
    __syncthreads();
    mx = red[0];
    #pragma unroll
    for (int i = 1; i < 8; i++) mx = fmaxf(mx, red[i]);
    __syncthreads();

    v0.x = expf(v0.x - mx); v0.y = expf(v0.y - mx);
    v0.z = expf(v0.z - mx); v0.w = expf(v0.w - mx);
    v1.x = expf(v1.x - mx); v1.y = expf(v1.y - mx);
    v1.z = expf(v1.z - mx); v1.w = expf(v1.w - mx);

    float s = (v0.x + v0.y + v0.z + v0.w) + (v1.x + v1.y + v1.z + v1.w);
    s = warp_sum(s);
    if (lane == 0) red[wid] = s;
    __syncthreads();
    s = red[0];
    #pragma unroll
    for (int i = 1; i < 8; i++) s += red[i];

    const float inv = 1.0f / s;
    v0.x = to_tf32(v0.x * inv); v0.y = to_tf32(v0.y * inv);
    v0.z = to_tf32(v0.z * inv); v0.w = to_tf32(v0.w * inv);
    v1.x = to_tf32(v1.x * inv); v1.y = to_tf32(v1.y * inv);
    v1.z = to_tf32(v1.z * inv); v1.w = to_tf32(v1.w * inv);
    ((float4*)p)[t]       = v0;
    ((float4*)p)[256 + t] = v1;
}

// single add+LN (used for final output)
__global__ __launch_bounds__(256)
void add_ln1024(const float* __restrict__ A, const float* __restrict__ R,
                const float* __restrict__ gamma, const float* __restrict__ beta,
                float* __restrict__ out)
{
    const size_t row = blockIdx.x;
    const int t = threadIdx.x, lane = t & 31, wid = t >> 5;
    __shared__ float rs[8], rq[8];

    float4 a = ((const float4*)(A + row * 1024))[t];
    float4 r = ((const float4*)(R + row * 1024))[t];
    float h0 = a.x + r.x, h1 = a.y + r.y, h2 = a.z + r.z, h3 = a.w + r.w;

    float s = h0 + h1 + h2 + h3;
    float q = h0 * h0 + h1 * h1 + h2 * h2 + h3 * h3;
    s = warp_sum(s); q = warp_sum(q);
    if (lane == 0) { rs[wid] = s; rq[wid] = q; }
    __syncthreads();
    s = rs[0]; q = rq[0];
    #pragma unroll
    for (int i = 1; i < 8; i++) { s += rs[i]; q += rq[i]; }

    const float mean = s * (1.0f / 1024.0f);
    const float var  = q * (1.0f / 1024.0f) - mean * mean;
    const float rstd = rsqrtf(var + LN_EPS);

    float4 gg = ((const float4*)gamma)[t];
    float4 bb = ((const float4*)beta)[t];
    float4 o;
    o.x = (h0 - mean) * rstd * gg.x + bb.x;
    o.y = (h1 - mean) * rstd * gg.y + bb.y;
    o.z = (h2 - mean) * rstd * gg.z + bb.z;
    o.w = (h3 - mean) * rstd * gg.w + bb.w;
    ((float4*)(out + row * 1024))[t] = o;
}

// fused: at = LN(O + x)*g_at+b_at;  H = LN(at + x)*g_ln+b_ln;  Hr = tf32(H)
__global__ __launch_bounds__(256)
void ln2_fused(const float* __restrict__ O, const float* __restrict__ X,
               const float* __restrict__ gat, const float* __restrict__ bat,
               const float* __restrict__ gln, const float* __restrict__ bln,
               float* __restrict__ H, float* __restrict__ Hr)
{
    const size_t row = blockIdx.x;
    const int t = threadIdx.x, lane = t & 31, wid = t >> 5;
    __shared__ float rs[8], rq[8];

    float4 a = ((const float4*)(O + row * 1024))[t];
    float4 xv = ((const float4*)(X + row * 1024))[t];
    float h[4] = {a.x + xv.x, a.y + xv.y, a.z + xv.z, a.w + xv.w};

    // --- LN 1 ---
    float s = h[0] + h[1] + h[2] + h[3];
    float q = h[0]*h[0] + h[1]*h[1] + h[2]*h[2] + h[3]*h[3];
    s = warp_sum(s); q = warp_sum(q);
    if (lane == 0) { rs[wid] = s; rq[wid] = q; }
    __syncthreads();
    s = rs[0]; q = rq[0];
    #pragma unroll
    for (int i = 1; i < 8; i++) { s += rs[i]; q += rq[i]; }
    float mean = s * (1.0f / 1024.0f);
    float var  = q * (1.0f / 1024.0f) - mean * mean;
    float rstd = rsqrtf(var + LN_EPS);

    float4 g1 = ((const float4*)gat)[t];
    float4 b1 = ((const float4*)bat)[t];
    float u[4];
    u[0] = (h[0] - mean) * rstd * g1.x + b1.x + xv.x;
    u[1] = (h[1] - mean) * rstd * g1.y + b1.y + xv.y;
    u[2] = (h[2] - mean) * rstd * g1.z + b1.z + xv.z;
    u[3] = (h[3] - mean) * rstd * g1.w + b1.w + xv.w;
    __syncthreads();   // reuse smem

    // --- LN 2 ---
    s = u[0] + u[1] + u[2] + u[3];
    q = u[0]*u[0] + u[1]*u[1] + u[2]*u[2] + u[3]*u[3];
    s = warp_sum(s); q = warp_sum(q);
    if (lane == 0) { rs[wid] = s; rq[wid] = q; }
    __syncthreads();
    s = rs[0]; q = rq[0];
    #pragma unroll
    for (int i = 1; i < 8; i++) { s += rs[i]; q += rq[i]; }
    mean = s * (1.0f / 1024.0f);
    var  = q * (1.0f / 1024.0f) - mean * mean;
    rstd = rsqrtf(var + LN_EPS);

    float4 g2 = ((const float4*)gln)[t];
    float4 b2 = ((const float4*)bln)[t];
    float4 o, orr;
    o.x = (u[0] - mean) * rstd * g2.x + b2.x;
    o.y = (u[1] - mean) * rstd * g2.y + b2.y;
    o.z = (u[2] - mean) * rstd * g2.z + b2.z;
    o.w = (u[3] - mean) * rstd * g2.w + b2.w;
    orr.x = to_tf32(o.x); orr.y = to_tf32(o.y);
    orr.z = to_tf32(o.z); orr.w = to_tf32(o.w);
    ((float4*)(H  + row * 1024))[t] = o;
    ((float4*)(Hr + row * 1024))[t] = orr;
}

// ---------------- launcher ---------------------------------------------------
extern "C" void kernel_launch(void* const* d_in, const int* in_sizes, int n_in,
                              void* d_out, int out_size)
{
    const float* x   = (const float*)d_in[0];
    const float* Wq  = (const float*)d_in[1];
    const float* bq  = (const float*)d_in[2];
    const float* Wk  = (const float*)d_in[3];
    const float* bk  = (const float*)d_in[4];
    const float* Wv  = (const float*)d_in[5];
    const float* bv  = (const float*)d_in[6];
    const float* gat = (const float*)d_in[7];
    const float* bat = (const float*)d_in[8];
    const float* gln = (const float*)d_in[9];
    const float* bln = (const float*)d_in[10];
    const float* W1  = (const float*)d_in[11];
    const float* c1  = (const float*)d_in[12];
    const float* W2  = (const float*)d_in[13];
    const float* c2  = (const float*)d_in[14];
    float* out = (float*)d_out;

    float *xr, *WqT, *WkT, *WvT, *W1T, *W2T, *Q, *K, *V, *VT, *P, *O, *H, *Hr, *H1, *H2;
    cudaGetSymbolAddress((void**)&xr,  g_xr);
    cudaGetSymbolAddress((void**)&WqT, g_WqT);
    cudaGetSymbolAddress((void**)&WkT, g_WkT);
    cudaGetSymbolAddress((void**)&WvT, g_WvT);
    cudaGetSymbolAddress((void**)&W1T, g_W1T);
    cudaGetSymbolAddress((void**)&W2T, g_W2T);
    cudaGetSymbolAddress((void**)&Q,   g_Q);
    cudaGetSymbolAddress((void**)&K,   g_K);
    cudaGetSymbolAddress((void**)&V,   g_V);
    cudaGetSymbolAddress((void**)&VT,  g_VT);
    cudaGetSymbolAddress((void**)&P,   g_P);
    cudaGetSymbolAddress((void**)&O,   g_O);
    cudaGetSymbolAddress((void**)&H,   g_H);
    cudaGetSymbolAddress((void**)&Hr,  g_Hr);
    cudaGetSymbolAddress((void**)&H1,  g_H1);
    cudaGetSymbolAddress((void**)&H2,  g_H2);

    cudaFuncSetAttribute(tgemm<0,0>, cudaFuncAttributeMaxDynamicSharedMemorySize, SMEM_BYTES);
    cudaFuncSetAttribute(tgemm<0,1>, cudaFuncAttributeMaxDynamicSharedMemorySize, SMEM_BYTES);
    cudaFuncSetAttribute(tgemm<1,0>, cudaFuncAttributeMaxDynamicSharedMemorySize, SMEM_BYTES);
    cudaFuncSetAttribute(tgemm<1,1>, cudaFuncAttributeMaxDynamicSharedMemorySize, SMEM_BYTES);

    const dim3 blk(256);
    const size_t sSD = (size_t)SS * DD;
    const size_t sSS = (size_t)SS * SS;

    // 1: round x
    round_copy<<<(MTOT * DD / 4 + 255) / 256, blk>>>(x, xr, (size_t)MTOT * DD / 4);
    // 2: all weight transposes in one launch
    transpose5<<<dim3(32, 32, 5), dim3(32, 8)>>>(Wq, Wk, Wv, W1, W2,
                                                 WqT, WkT, WvT, W1T, W2T);

    const dim3 gQKV(DD / 128, MTOT / 128, 1);      // (8, 64)
    const dim3 gSC (SS / 128, SS / 128, BB);       // (16, 16, 4)
    const dim3 gPV (DD / 128, SS / 128, BB);       // (8, 16, 4)

    // 3-5: QKV projections
    tgemm<0,1><<<gQKV, blk, SMEM_BYTES>>>(xr, WqT, bq, Q, DD, DD, DD, DD, 1.0f, 0, 0, 0);
    tgemm<0,1><<<gQKV, blk, SMEM_BYTES>>>(xr, WkT, bk, K, DD, DD, DD, DD, 1.0f, 0, 0, 0);
    tgemm<0,0><<<gQKV, blk, SMEM_BYTES>>>(xr, WvT, bv, V, DD, DD, DD, DD, 1.0f, 0, 0, 0);

    // 6: scores = (Q @ K^T) / 8
    tgemm<0,0><<<gSC, blk, SMEM_BYTES>>>(Q, K, nullptr, P, DD, DD, SS, DD, INV_SCALE, sSD, sSD, sSS);

    // 7: V^T per batch: [S,D] -> [D,S], rounded
    transpose_round<<<dim3(DD / 32, SS / 32, BB), dim3(32, 8)>>>(V, VT, SS, DD, sSD, sSD);

    // 8: softmax (rounds P to tf32 at store)
    softmax2048<<<BB * SS, blk>>>(P);

    // 9: O = P @ V  (B = V^T stored [D,S])
    tgemm<0,0><<<gPV, blk, SMEM_BYTES>>>(P, VT, nullptr, O, SS, SS, DD, SS, 1.0f, sSS, sSD, sSD);

    // 10: fused double-LN: H = LN(LN(O+x)+x), Hr = tf32(H)
    ln2_fused<<<MTOT, blk>>>(O, x, gat, bat, gln, bln, H, Hr);

    // 11-12: FFN
    tgemm<1,1><<<gQKV, blk, SMEM_BYTES>>>(Hr, W1T, c1, H1, DD, DD, DD, DD, 1.0f, 0, 0, 0);
    tgemm<1,0><<<gQKV, blk, SMEM_BYTES>>>(H1, W2T, c2, H2, DD, DD, DD, DD, 1.0f, 0, 0, 0);

    // 13: out = LN(h2 + h)
    add_ln1024<<<MTOT, blk>>>(H2, H, gln, bln, out);
}